// round 6
// baseline (speedup 1.0000x reference)
#include <cuda_runtime.h>
#include <math.h>
#include <stdint.h>

// Problem constants (fixed by setup_inputs)
#define NN 131072      // nodes
#define NE 2097152     // edges
#define NG 2048        // graphs
#define DIN 64         // input_dim
#define DH  128        // hidden dim

#define SCAN_BLOCKS 512
#define SCAN_TPB    256          // SCAN_BLOCKS * SCAN_TPB == NN

// ---------------- scratch (device globals; no allocation allowed) ----------
__device__ float g_hA[(size_t)NN * DH];
__device__ float g_hB[(size_t)NN * DH];
__device__ float g_hfc[(size_t)NN * DIN];
__device__ float g_gi[(size_t)NN * 3];
__device__ int   g_deg[NN];
__device__ int   g_off[NN + 1];
__device__ int   g_cur[NN];
__device__ int   g_src[NE];
__device__ int   g_bsum[SCAN_BLOCKS];
__device__ int   g_boff[SCAN_BLOCKS];

__device__ __forceinline__ float gelu_exact(float x) {
    return 0.5f * x * (1.0f + erff(x * 0.70710678118654752f));
}

// ---- packed fp32x2 helpers (full-rate FMA path on sm_103a) -----------------
__device__ __forceinline__ unsigned long long pack2(float x, float y) {
    unsigned long long r;
    asm("mov.b64 %0, {%1, %2};" : "=l"(r) : "f"(x), "f"(y));
    return r;
}
__device__ __forceinline__ void ffma2(unsigned long long& d,
                                      unsigned long long a,
                                      unsigned long long b) {
    asm("fma.rn.f32x2 %0, %1, %2, %0;" : "+l"(d) : "l"(a), "l"(b));
}
__device__ __forceinline__ float2 unpack2(unsigned long long v) {
    float2 f;
    asm("mov.b64 {%0, %1}, %2;" : "=f"(f.x), "=f"(f.y) : "l"(v));
    return f;
}

// ---------------- 1. embed + concat + L2 normalize -> g_hA ------------------
__global__ void embed_norm_kernel(const float* __restrict__ x,
                                  const float* __restrict__ emb,
                                  float* __restrict__ hout) {
    int idx  = blockIdx.x * blockDim.x + threadIdx.x;
    int node = idx >> 5;
    int lane = idx & 31;
    if (node >= NN) return;

    const float* xr = x + (size_t)node * 65;
    int id = (int)xr[64];

    float v[4];
    int base = lane * 4;
#pragma unroll
    for (int j = 0; j < 4; j++) {
        int c = base + j;
        v[j] = (c < 64) ? xr[c] : emb[(size_t)id * 64 + (c - 64)];
    }
    float ss = v[0] * v[0] + v[1] * v[1] + v[2] * v[2] + v[3] * v[3];
#pragma unroll
    for (int o = 16; o > 0; o >>= 1) ss += __shfl_xor_sync(0xFFFFFFFFu, ss, o);
    float inv = 1.0f / sqrtf(ss);

    float4 o;
    o.x = v[0] * inv; o.y = v[1] * inv; o.z = v[2] * inv; o.w = v[3] * inv;
    *(float4*)&hout[(size_t)node * DH + base] = o;
}

// ---------------- 2. CSR build ----------------------------------------------
__global__ void zero_deg_kernel() {
    int i = blockIdx.x * blockDim.x + threadIdx.x;
    if (i < NN) g_deg[i] = 0;
}

__global__ void hist_kernel(const int* __restrict__ ei) {
    int e = blockIdx.x * blockDim.x + threadIdx.x;
    if (e < NE) atomicAdd(&g_deg[ei[NE + e]], 1);
}

__global__ void scan_phase1() {
    __shared__ int sh[SCAN_TPB];
    int b = blockIdx.x, t = threadIdx.x;
    sh[t] = g_deg[b * SCAN_TPB + t];
    __syncthreads();
#pragma unroll
    for (int d = SCAN_TPB / 2; d > 0; d >>= 1) {
        if (t < d) sh[t] += sh[t + d];
        __syncthreads();
    }
    if (t == 0) g_bsum[b] = sh[0];
}

__global__ void scan_phase2() {
    __shared__ int sh[SCAN_BLOCKS];
    int t = threadIdx.x;
    sh[t] = g_bsum[t];
    __syncthreads();
#pragma unroll
    for (int d = 1; d < SCAN_BLOCKS; d <<= 1) {
        int v = (t >= d) ? sh[t - d] : 0;
        __syncthreads();
        sh[t] += v;
        __syncthreads();
    }
    g_boff[t] = (t == 0) ? 0 : sh[t - 1];
}

__global__ void scan_phase3() {
    __shared__ int sh[SCAN_TPB];
    int b = blockIdx.x, t = threadIdx.x;
    int i = b * SCAN_TPB + t;
    int d = g_deg[i];
    sh[t] = d;
    __syncthreads();
#pragma unroll
    for (int s = 1; s < SCAN_TPB; s <<= 1) {
        int v = (t >= s) ? sh[t - s] : 0;
        __syncthreads();
        sh[t] += v;
        __syncthreads();
    }
    int off = g_boff[b] + sh[t] - d;   // exclusive
    g_off[i] = off;
    g_cur[i] = off;
    if (i == NN - 1) g_off[NN] = off + d;
}

__global__ void fill_kernel(const int* __restrict__ ei) {
    int e = blockIdx.x * blockDim.x + threadIdx.x;
    if (e < NE) {
        int s = ei[e];
        int d = ei[NE + e];
        int p = atomicAdd(&g_cur[d], 1);
        g_src[p] = s;
    }
}

// ---------------- 3. fused conv: gather-aggregate + dual GEMM + GELU --------
// C[i] = gelu( (sum_{j->i} h[j]) @ W_rel + h[i] @ W_root + bias )
// Block = 128 nodes. Phase A: gather neighbor sums into smem Agg[128][132].
// Phase B: 8 k-tiles of 32 (4 from Agg smem / W_rel, 4 from hin global / W_root),
// microtile 8x8 per thread, packed f32x2 accumulators (pairs along columns).
#define AGG_PAD 132
#define AS2_PAD 36
#define SM_AGG_F (128 * AGG_PAD)           // 16896 floats
#define SM_AS2_F (128 * AS2_PAD)           // 4608
#define SM_BS_F  (32 * 128)                // 4096
#define CONV_SMEM_BYTES ((SM_AGG_F + SM_AS2_F + SM_BS_F) * 4)   // 102400

__global__ __launch_bounds__(256, 2)
void conv_fused_kernel(const float* __restrict__ hin,
                       const float* __restrict__ Wrel,
                       const float* __restrict__ Wroot,
                       const float* __restrict__ bias,
                       float* __restrict__ C) {
    extern __shared__ float sm[];
    float* Agg = sm;                       // [128][AGG_PAD], row-major (m,k)
    float* As2 = sm + SM_AGG_F;            // [128][AS2_PAD], row-major (m,k-tile)
    float* Bs  = sm + SM_AGG_F + SM_AS2_F; // [32][128]

    int tid  = threadIdx.x;
    int wid  = tid >> 5;
    int lane = tid & 31;
    int tx = tid & 15;     // col group (8 cols)
    int ty = tid >> 4;     // row group (8 rows)
    int M0 = blockIdx.x * 128;

    // -------- Phase A: gather neighbor sums into Agg --------
    for (int mi = wid; mi < 128; mi += 8) {
        int node = M0 + mi;
        int beg = g_off[node], end = g_off[node + 1];
        float4 acc = make_float4(0.f, 0.f, 0.f, 0.f);
        int e = beg;
#pragma unroll 1
        for (; e + 4 <= end; e += 4) {
            int s0 = g_src[e], s1 = g_src[e + 1], s2 = g_src[e + 2], s3 = g_src[e + 3];
            float4 v0 = __ldg((const float4*)&hin[(size_t)s0 * DH + lane * 4]);
            float4 v1 = __ldg((const float4*)&hin[(size_t)s1 * DH + lane * 4]);
            float4 v2 = __ldg((const float4*)&hin[(size_t)s2 * DH + lane * 4]);
            float4 v3 = __ldg((const float4*)&hin[(size_t)s3 * DH + lane * 4]);
            acc.x += v0.x; acc.y += v0.y; acc.z += v0.z; acc.w += v0.w;
            acc.x += v1.x; acc.y += v1.y; acc.z += v1.z; acc.w += v1.w;
            acc.x += v2.x; acc.y += v2.y; acc.z += v2.z; acc.w += v2.w;
            acc.x += v3.x; acc.y += v3.y; acc.z += v3.z; acc.w += v3.w;
        }
        for (; e < end; e++) {
            int s = g_src[e];
            float4 v = __ldg((const float4*)&hin[(size_t)s * DH + lane * 4]);
            acc.x += v.x; acc.y += v.y; acc.z += v.z; acc.w += v.w;
        }
        *(float4*)&Agg[mi * AGG_PAD + lane * 4] = acc;
    }
    __syncthreads();

    // -------- Phase B: dual GEMM --------
    unsigned long long acc2[8][4];
#pragma unroll
    for (int r = 0; r < 8; r++)
#pragma unroll
        for (int c = 0; c < 4; c++) acc2[r][c] = 0ull;

    for (int kt = 0; kt < 8; kt++) {
        bool root = (kt >= 4);
        int kb = (kt & 3) * 32;
        const float* Bsrc = root ? Wroot : Wrel;

        // stage B tile (and A2 rows when root) into registers
        float4 bv[4];
#pragma unroll
        for (int i = 0; i < 4; i++) {
            int f = tid + i * 256;
            int k = f >> 5, c4 = f & 31;
            bv[i] = __ldg((const float4*)&Bsrc[(size_t)(kb + k) * 128 + c4 * 4]);
        }
        float4 av[4];
        if (root) {
#pragma unroll
            for (int i = 0; i < 4; i++) {
                int f = tid + i * 256;
                int m = f >> 3, kq = f & 7;
                av[i] = __ldg((const float4*)&hin[(size_t)(M0 + m) * 128 + kb + kq * 4]);
            }
        }

        __syncthreads();   // previous tile's compute done
#pragma unroll
        for (int i = 0; i < 4; i++) {
            int f = tid + i * 256;
            int k = f >> 5, c4 = f & 31;
            *(float4*)&Bs[k * 128 + c4 * 4] = bv[i];
        }
        if (root) {
#pragma unroll
            for (int i = 0; i < 4; i++) {
                int f = tid + i * 256;
                int m = f >> 3, kq = f & 7;
                *(float4*)&As2[m * AS2_PAD + kq * 4] = av[i];
            }
        }
        __syncthreads();

        if (!root) {
            const float* Ab = &Agg[(ty * 8) * AGG_PAD + kb];
#pragma unroll 4
            for (int kk = 0; kk < 32; kk++) {
                ulonglong2 b01 = *(const ulonglong2*)&Bs[kk * 128 + tx * 8];
                ulonglong2 b23 = *(const ulonglong2*)&Bs[kk * 128 + tx * 8 + 4];
#pragma unroll
                for (int r = 0; r < 8; r++) {
                    float a = Ab[r * AGG_PAD + kk];
                    unsigned long long a2 = pack2(a, a);
                    ffma2(acc2[r][0], a2, b01.x);
                    ffma2(acc2[r][1], a2, b01.y);
                    ffma2(acc2[r][2], a2, b23.x);
                    ffma2(acc2[r][3], a2, b23.y);
                }
            }
        } else {
            const float* Ab = &As2[(ty * 8) * AS2_PAD];
#pragma unroll 4
            for (int kk = 0; kk < 32; kk++) {
                ulonglong2 b01 = *(const ulonglong2*)&Bs[kk * 128 + tx * 8];
                ulonglong2 b23 = *(const ulonglong2*)&Bs[kk * 128 + tx * 8 + 4];
#pragma unroll
                for (int r = 0; r < 8; r++) {
                    float a = Ab[r * AS2_PAD + kk];
                    unsigned long long a2 = pack2(a, a);
                    ffma2(acc2[r][0], a2, b01.x);
                    ffma2(acc2[r][1], a2, b01.y);
                    ffma2(acc2[r][2], a2, b23.x);
                    ffma2(acc2[r][3], a2, b23.y);
                }
            }
        }
    }

    // -------- epilogue: bias + exact GELU --------
    float bb[8];
#pragma unroll
    for (int j = 0; j < 8; j++) bb[j] = __ldg(&bias[tx * 8 + j]);

#pragma unroll
    for (int r = 0; r < 8; r++) {
        int row = M0 + ty * 8 + r;
        float o[8];
#pragma unroll
        for (int c2 = 0; c2 < 4; c2++) {
            float2 f = unpack2(acc2[r][c2]);
            o[c2 * 2]     = gelu_exact(f.x + bb[c2 * 2]);
            o[c2 * 2 + 1] = gelu_exact(f.y + bb[c2 * 2 + 1]);
        }
        *(float4*)&C[(size_t)row * 128 + tx * 8]     = make_float4(o[0], o[1], o[2], o[3]);
        *(float4*)&C[(size_t)row * 128 + tx * 8 + 4] = make_float4(o[4], o[5], o[6], o[7]);
    }
}

// ---------------- 4. fc GEMM (128 -> 64) + bias + GELU ----------------------
// A [NN,128], B [128,64]. Row-pairs packed along M into f32x2 accumulators.
__global__ __launch_bounds__(256, 2)
void fc_gemm_kernel(const float* __restrict__ A,
                    const float* __restrict__ B,
                    const float* __restrict__ bias,
                    float* __restrict__ C) {
    __shared__ float As[32 * 132];   // transposed A tile [k][m], pad 132
    __shared__ float Bs[32 * 64];

    int tid = threadIdx.x;
    int tx = tid & 15;     // 4 cols per thread
    int ty = tid >> 4;     // 8 rows per thread
    int M0 = blockIdx.x * 128;

    unsigned long long acc2[4][4];   // [row-pair][col]
#pragma unroll
    for (int r = 0; r < 4; r++)
#pragma unroll
        for (int c = 0; c < 4; c++) acc2[r][c] = 0ull;

    for (int kt = 0; kt < 4; kt++) {
        int kb = kt * 32;

        float4 av[4];
#pragma unroll
        for (int i = 0; i < 4; i++) {
            int f = tid + i * 256;
            int m = f >> 3, kq = f & 7;
            av[i] = __ldg((const float4*)&A[(size_t)(M0 + m) * 128 + kb + kq * 4]);
        }
        float4 bv[2];
#pragma unroll
        for (int i = 0; i < 2; i++) {
            int f = tid + i * 256;
            int k = f >> 4, c4 = f & 15;
            bv[i] = __ldg((const float4*)&B[(size_t)(kb + k) * 64 + c4 * 4]);
        }

        __syncthreads();
#pragma unroll
        for (int i = 0; i < 4; i++) {
            int f = tid + i * 256;
            int m = f >> 3, kq = f & 7;
            As[(kq * 4 + 0) * 132 + m] = av[i].x;
            As[(kq * 4 + 1) * 132 + m] = av[i].y;
            As[(kq * 4 + 2) * 132 + m] = av[i].z;
            As[(kq * 4 + 3) * 132 + m] = av[i].w;
        }
#pragma unroll
        for (int i = 0; i < 2; i++) {
            int f = tid + i * 256;
            int k = f >> 4, c4 = f & 15;
            *(float4*)&Bs[k * 64 + c4 * 4] = bv[i];
        }
        __syncthreads();

#pragma unroll 4
        for (int kk = 0; kk < 32; kk++) {
            ulonglong2 a01 = *(const ulonglong2*)&As[kk * 132 + ty * 8];
            ulonglong2 a23 = *(const ulonglong2*)&As[kk * 132 + ty * 8 + 4];
            float4 bf = *(const float4*)&Bs[kk * 64 + tx * 4];
            unsigned long long b2[4];
            b2[0] = pack2(bf.x, bf.x);
            b2[1] = pack2(bf.y, bf.y);
            b2[2] = pack2(bf.z, bf.z);
            b2[3] = pack2(bf.w, bf.w);
#pragma unroll
            for (int c = 0; c < 4; c++) {
                ffma2(acc2[0][c], a01.x, b2[c]);
                ffma2(acc2[1][c], a01.y, b2[c]);
                ffma2(acc2[2][c], a23.x, b2[c]);
                ffma2(acc2[3][c], a23.y, b2[c]);
            }
        }
    }

    float bb[4];
#pragma unroll
    for (int j = 0; j < 4; j++) bb[j] = __ldg(&bias[tx * 4 + j]);

#pragma unroll
    for (int r2 = 0; r2 < 4; r2++) {
        float ox[4], oy[4];
#pragma unroll
        for (int c = 0; c < 4; c++) {
            float2 f = unpack2(acc2[r2][c]);
            ox[c] = gelu_exact(f.x + bb[c]);
            oy[c] = gelu_exact(f.y + bb[c]);
        }
        int row0 = M0 + ty * 8 + r2 * 2;
        *(float4*)&C[(size_t)row0 * 64 + tx * 4]       = make_float4(ox[0], ox[1], ox[2], ox[3]);
        *(float4*)&C[(size_t)(row0 + 1) * 64 + tx * 4] = make_float4(oy[0], oy[1], oy[2], oy[3]);
    }
}

// ---------------- 5. GRU input gates ----------------------------------------
__global__ void gi_kernel(const float* __restrict__ W_ih,
                          const float* __restrict__ b_ih) {
    int idx  = blockIdx.x * blockDim.x + threadIdx.x;
    int node = idx >> 5;
    int lane = idx & 31;
    if (node >= NN) return;
    float2 v = *(const float2*)&g_hfc[(size_t)node * DIN + lane * 2];
    float d0 = v.x * W_ih[lane * 2] + v.y * W_ih[lane * 2 + 1];
    float d1 = v.x * W_ih[64 + lane * 2] + v.y * W_ih[64 + lane * 2 + 1];
    float d2 = v.x * W_ih[128 + lane * 2] + v.y * W_ih[128 + lane * 2 + 1];
#pragma unroll
    for (int o = 16; o > 0; o >>= 1) {
        d0 += __shfl_xor_sync(0xFFFFFFFFu, d0, o);
        d1 += __shfl_xor_sync(0xFFFFFFFFu, d1, o);
        d2 += __shfl_xor_sync(0xFFFFFFFFu, d2, o);
    }
    if (lane == 0) {
        g_gi[(size_t)node * 3 + 0] = d0 + b_ih[0];
        g_gi[(size_t)node * 3 + 1] = d1 + b_ih[1];
        g_gi[(size_t)node * 3 + 2] = d2 + b_ih[2];
    }
}

// ---------------- 6. GRU scan (H=1) + last-nonzero select -------------------
__global__ void gru_scan_kernel(const float* __restrict__ W_hh,
                                const float* __restrict__ b_hh,
                                const float* __restrict__ init,
                                float* __restrict__ out) {
    int g = blockIdx.x * blockDim.x + threadIdx.x;
    if (g >= NG) return;
    float whr = W_hh[0], whz = W_hh[1], whn = W_hh[2];
    float bhr = b_hh[0], bhz = b_hh[1], bhn = b_hh[2];
    float h = init[0];
    float v0 = 0.f, lastVal = 0.f, sum = 0.f;
    int lastIdx = -1;
    const float* gp = &g_gi[(size_t)g * 64 * 3];
    for (int t = 0; t < 64; t++) {
        float gir = gp[t * 3 + 0];
        float giz = gp[t * 3 + 1];
        float gin = gp[t * 3 + 2];
        float r = 1.0f / (1.0f + expf(-(gir + whr * h + bhr)));
        float z = 1.0f / (1.0f + expf(-(giz + whz * h + bhz)));
        float n = tanhf(gin + r * (whn * h + bhn));
        h = (1.0f - z) * n + z * h;
        float m = h;  // mask == 1 (every graph has exactly 64 nodes)
        if (t == 0) v0 = m;
        if (m != 0.0f) { lastIdx = t; lastVal = m; }
        sum += m;
    }
    out[g] = (sum > 0.0f && lastIdx >= 0) ? lastVal : v0;
}

// ---------------- launch -----------------------------------------------------
extern "C" void kernel_launch(void* const* d_in, const int* in_sizes, int n_in,
                              void* d_out, int out_size) {
    (void)in_sizes; (void)n_in; (void)out_size;

    const float* x       = (const float*)d_in[0];
    const float* emb     = (const float*)d_in[1];
    const float* W_rel1  = (const float*)d_in[2];
    const float* b_rel1  = (const float*)d_in[3];
    const float* W_root1 = (const float*)d_in[4];
    const float* W_rel2  = (const float*)d_in[5];
    const float* b_rel2  = (const float*)d_in[6];
    const float* W_root2 = (const float*)d_in[7];
    const float* W_rel3  = (const float*)d_in[8];
    const float* b_rel3  = (const float*)d_in[9];
    const float* W_root3 = (const float*)d_in[10];
    const float* W_fc    = (const float*)d_in[11];
    const float* b_fc    = (const float*)d_in[12];
    const float* W_ih    = (const float*)d_in[13];
    const float* W_hh    = (const float*)d_in[14];
    const float* b_ih    = (const float*)d_in[15];
    const float* b_hh    = (const float*)d_in[16];
    const float* init    = (const float*)d_in[17];
    const int*   ei      = (const int*)d_in[18];
    float*       out     = (float*)d_out;

    float *hA, *hB, *hfc;
    cudaGetSymbolAddress((void**)&hA,  g_hA);
    cudaGetSymbolAddress((void**)&hB,  g_hB);
    cudaGetSymbolAddress((void**)&hfc, g_hfc);

    cudaFuncSetAttribute(conv_fused_kernel,
                         cudaFuncAttributeMaxDynamicSharedMemorySize,
                         CONV_SMEM_BYTES);

    const int T = 256;

    // embedding + normalize, CSR build
    zero_deg_kernel<<<(NN + T - 1) / T, T>>>();
    embed_norm_kernel<<<NN / 8, T>>>(x, emb, hA);
    hist_kernel<<<NE / T, T>>>(ei);
    scan_phase1<<<SCAN_BLOCKS, SCAN_TPB>>>();
    scan_phase2<<<1, SCAN_BLOCKS>>>();
    scan_phase3<<<SCAN_BLOCKS, SCAN_TPB>>>();
    fill_kernel<<<NE / T, T>>>(ei);

    // fused conv layers (gather + dual GEMM + GELU)
    conv_fused_kernel<<<NN / 128, T, CONV_SMEM_BYTES>>>(hA, W_rel1, W_root1, b_rel1, hB);
    conv_fused_kernel<<<NN / 128, T, CONV_SMEM_BYTES>>>(hB, W_rel2, W_root2, b_rel2, hA);
    conv_fused_kernel<<<NN / 128, T, CONV_SMEM_BYTES>>>(hA, W_rel3, W_root3, b_rel3, hB);

    // fc: hB -> hfc
    fc_gemm_kernel<<<NN / 128, T>>>(hB, W_fc, b_fc, hfc);

    // GRU
    gi_kernel<<<NN / 8, T>>>(W_ih, b_ih);
    gru_scan_kernel<<<NG / T, T>>>(W_hh, b_hh, init, out);
}

// round 7
// speedup vs baseline: 1.2883x; 1.2883x over previous
#include <cuda_runtime.h>
#include <math.h>
#include <stdint.h>

// Problem constants (fixed by setup_inputs)
#define NN 131072      // nodes
#define NE 2097152     // edges
#define NG 2048        // graphs
#define DIN 64         // input_dim
#define DH  128        // hidden dim

#define SCAN_BLOCKS 512
#define SCAN_TPB    256          // SCAN_BLOCKS * SCAN_TPB == NN

// ---------------- scratch (device globals; no allocation allowed) ----------
__device__ float g_hA[(size_t)NN * DH];
__device__ float g_hB[(size_t)NN * DH];
__device__ float g_agg[(size_t)NN * DH];
__device__ float g_hfc[(size_t)NN * DIN];
__device__ float g_gi[(size_t)NN * 3];
__device__ int   g_deg[NN];
__device__ int   g_off[NN + 1];
__device__ int   g_cur[NN];
__device__ int   g_src[NE];
__device__ int   g_bsum[SCAN_BLOCKS];
__device__ int   g_boff[SCAN_BLOCKS];

__device__ __forceinline__ float gelu_exact(float x) {
    return 0.5f * x * (1.0f + erff(x * 0.70710678118654752f));
}

// ---- packed fp32x2 helpers (FFMA2 path on sm_103a) --------------------------
__device__ __forceinline__ unsigned long long pack2(float x, float y) {
    unsigned long long r;
    asm("mov.b64 %0, {%1, %2};" : "=l"(r) : "f"(x), "f"(y));
    return r;
}
__device__ __forceinline__ void ffma2(unsigned long long& d,
                                      unsigned long long a,
                                      unsigned long long b) {
    asm("fma.rn.f32x2 %0, %1, %2, %0;" : "+l"(d) : "l"(a), "l"(b));
}
__device__ __forceinline__ float2 unpack2(unsigned long long v) {
    float2 f;
    asm("mov.b64 {%0, %1}, %2;" : "=f"(f.x), "=f"(f.y) : "l"(v));
    return f;
}

// ---------------- 1. embed + concat + L2 normalize -> g_hA ------------------
__global__ void embed_norm_kernel(const float* __restrict__ x,
                                  const float* __restrict__ emb,
                                  float* __restrict__ hout) {
    int idx  = blockIdx.x * blockDim.x + threadIdx.x;
    int node = idx >> 5;
    int lane = idx & 31;
    if (node >= NN) return;

    const float* xr = x + (size_t)node * 65;
    int id = (int)xr[64];

    float v[4];
    int base = lane * 4;
#pragma unroll
    for (int j = 0; j < 4; j++) {
        int c = base + j;
        v[j] = (c < 64) ? xr[c] : emb[(size_t)id * 64 + (c - 64)];
    }
    float ss = v[0] * v[0] + v[1] * v[1] + v[2] * v[2] + v[3] * v[3];
#pragma unroll
    for (int o = 16; o > 0; o >>= 1) ss += __shfl_xor_sync(0xFFFFFFFFu, ss, o);
    float inv = 1.0f / sqrtf(ss);

    float4 o;
    o.x = v[0] * inv; o.y = v[1] * inv; o.z = v[2] * inv; o.w = v[3] * inv;
    *(float4*)&hout[(size_t)node * DH + base] = o;
}

// ---------------- 2. CSR build ----------------------------------------------
__global__ void zero_deg_kernel() {
    int i = blockIdx.x * blockDim.x + threadIdx.x;
    if (i < NN) g_deg[i] = 0;
}

__global__ void hist_kernel(const int* __restrict__ ei) {
    int e = blockIdx.x * blockDim.x + threadIdx.x;
    if (e < NE) atomicAdd(&g_deg[ei[NE + e]], 1);
}

__global__ void scan_phase1() {
    __shared__ int sh[SCAN_TPB];
    int b = blockIdx.x, t = threadIdx.x;
    sh[t] = g_deg[b * SCAN_TPB + t];
    __syncthreads();
#pragma unroll
    for (int d = SCAN_TPB / 2; d > 0; d >>= 1) {
        if (t < d) sh[t] += sh[t + d];
        __syncthreads();
    }
    if (t == 0) g_bsum[b] = sh[0];
}

__global__ void scan_phase2() {
    __shared__ int sh[SCAN_BLOCKS];
    int t = threadIdx.x;
    sh[t] = g_bsum[t];
    __syncthreads();
#pragma unroll
    for (int d = 1; d < SCAN_BLOCKS; d <<= 1) {
        int v = (t >= d) ? sh[t - d] : 0;
        __syncthreads();
        sh[t] += v;
        __syncthreads();
    }
    g_boff[t] = (t == 0) ? 0 : sh[t - 1];
}

__global__ void scan_phase3() {
    __shared__ int sh[SCAN_TPB];
    int b = blockIdx.x, t = threadIdx.x;
    int i = b * SCAN_TPB + t;
    int d = g_deg[i];
    sh[t] = d;
    __syncthreads();
#pragma unroll
    for (int s = 1; s < SCAN_TPB; s <<= 1) {
        int v = (t >= s) ? sh[t - s] : 0;
        __syncthreads();
        sh[t] += v;
        __syncthreads();
    }
    int off = g_boff[b] + sh[t] - d;   // exclusive
    g_off[i] = off;
    g_cur[i] = off;
    if (i == NN - 1) g_off[NN] = off + d;
}

__global__ void fill_kernel(const int* __restrict__ ei) {
    int e = blockIdx.x * blockDim.x + threadIdx.x;
    if (e < NE) {
        int s = ei[e];
        int d = ei[NE + e];
        int p = atomicAdd(&g_cur[d], 1);
        g_src[p] = s;
    }
}

// ---------------- 3. neighbor sum: agg[i] = sum_{j->i} h[j] ----------------
// One warp per node, each lane owns a float4 feature chunk. High block count
// keeps occupancy high enough to hide L2 latency (the round-5 fusion lost this).
__global__ void aggregate_kernel(const float* __restrict__ hin) {
    int idx  = blockIdx.x * blockDim.x + threadIdx.x;
    int node = idx >> 5;
    int lane = idx & 31;
    if (node >= NN) return;
    int beg = g_off[node], end = g_off[node + 1];
    float4 acc = make_float4(0.f, 0.f, 0.f, 0.f);
    int e = beg;
#pragma unroll 1
    for (; e + 4 <= end; e += 4) {
        int s0 = g_src[e], s1 = g_src[e + 1], s2 = g_src[e + 2], s3 = g_src[e + 3];
        float4 v0 = __ldg((const float4*)&hin[(size_t)s0 * DH + lane * 4]);
        float4 v1 = __ldg((const float4*)&hin[(size_t)s1 * DH + lane * 4]);
        float4 v2 = __ldg((const float4*)&hin[(size_t)s2 * DH + lane * 4]);
        float4 v3 = __ldg((const float4*)&hin[(size_t)s3 * DH + lane * 4]);
        acc.x += v0.x; acc.y += v0.y; acc.z += v0.z; acc.w += v0.w;
        acc.x += v1.x; acc.y += v1.y; acc.z += v1.z; acc.w += v1.w;
        acc.x += v2.x; acc.y += v2.y; acc.z += v2.z; acc.w += v2.w;
        acc.x += v3.x; acc.y += v3.y; acc.z += v3.z; acc.w += v3.w;
    }
    for (; e < end; e++) {
        int s = g_src[e];
        float4 v = __ldg((const float4*)&hin[(size_t)s * DH + lane * 4]);
        acc.x += v.x; acc.y += v.y; acc.z += v.z; acc.w += v.w;
    }
    *(float4*)&g_agg[(size_t)node * DH + lane * 4] = acc;
}

// ---------------- 4. dual GEMM + bias + GELU (f32x2 packed) ------------------
// C[i] = gelu( A1[i]@B1 + A2[i]@B2 + bias ), A*: [NN,128], B*: [128,128].
// M-tile 128, K-tile 32. 256 threads; thread microtile 8 rows x 8 cols with
// rows packed in pairs into f32x2 accumulators (A pairs read directly from the
// transposed smem tile; B broadcast-packed via mov.b64).
__global__ __launch_bounds__(256, 2)
void dual_gemm_gelu_kernel(const float* __restrict__ A1, const float* __restrict__ A2,
                           const float* __restrict__ B1, const float* __restrict__ B2,
                           const float* __restrict__ bias, float* __restrict__ C) {
    __shared__ float As[32 * 132];   // transposed A tile [k][m], pad 132
    __shared__ float Bs[32 * 128];

    int tid = threadIdx.x;
    int tx = tid & 15;     // col group (8 cols)
    int ty = tid >> 4;     // row group (8 rows = 4 row-pairs)
    int M0 = blockIdx.x * 128;

    unsigned long long acc2[4][8];   // [row-pair][col]
#pragma unroll
    for (int r = 0; r < 4; r++)
#pragma unroll
        for (int c = 0; c < 8; c++) acc2[r][c] = 0ull;

    for (int kt = 0; kt < 8; kt++) {
        const float* Asrc; const float* Bsrc; int kb;
        if (kt >= 4) { Asrc = A2; Bsrc = B2; kb = (kt - 4) * 32; }
        else         { Asrc = A1; Bsrc = B1; kb = kt * 32; }

        // stage global -> regs
        float4 av[4];
#pragma unroll
        for (int i = 0; i < 4; i++) {
            int f = tid + i * 256;          // 0..1023
            int m = f >> 3, kq = f & 7;
            av[i] = __ldg((const float4*)&Asrc[(size_t)(M0 + m) * 128 + kb + kq * 4]);
        }
        float4 bv[4];
#pragma unroll
        for (int i = 0; i < 4; i++) {
            int f = tid + i * 256;
            int k = f >> 5, c4 = f & 31;
            bv[i] = __ldg((const float4*)&Bsrc[(size_t)(kb + k) * 128 + c4 * 4]);
        }

        __syncthreads();   // previous tile's compute done
#pragma unroll
        for (int i = 0; i < 4; i++) {
            int f = tid + i * 256;
            int m = f >> 3, kq = f & 7;
            As[(kq * 4 + 0) * 132 + m] = av[i].x;
            As[(kq * 4 + 1) * 132 + m] = av[i].y;
            As[(kq * 4 + 2) * 132 + m] = av[i].z;
            As[(kq * 4 + 3) * 132 + m] = av[i].w;
        }
#pragma unroll
        for (int i = 0; i < 4; i++) {
            int f = tid + i * 256;
            int k = f >> 5, c4 = f & 31;
            *(float4*)&Bs[k * 128 + c4 * 4] = bv[i];
        }
        __syncthreads();

#pragma unroll 4
        for (int kk = 0; kk < 32; kk++) {
            // A row-pairs: 8 consecutive m values = 4 f32x2 pairs
            ulonglong2 a01 = *(const ulonglong2*)&As[kk * 132 + ty * 8];
            ulonglong2 a23 = *(const ulonglong2*)&As[kk * 132 + ty * 8 + 4];
            unsigned long long ap[4] = {a01.x, a01.y, a23.x, a23.y};
            // B scalars broadcast into pairs
            float4 b0 = *(const float4*)&Bs[kk * 128 + tx * 8];
            float4 b1 = *(const float4*)&Bs[kk * 128 + tx * 8 + 4];
            unsigned long long b2[8];
            b2[0] = pack2(b0.x, b0.x); b2[1] = pack2(b0.y, b0.y);
            b2[2] = pack2(b0.z, b0.z); b2[3] = pack2(b0.w, b0.w);
            b2[4] = pack2(b1.x, b1.x); b2[5] = pack2(b1.y, b1.y);
            b2[6] = pack2(b1.z, b1.z); b2[7] = pack2(b1.w, b1.w);
#pragma unroll
            for (int rp = 0; rp < 4; rp++)
#pragma unroll
                for (int c = 0; c < 8; c++)
                    ffma2(acc2[rp][c], ap[rp], b2[c]);
        }
    }

    // epilogue: bias + exact GELU
    float bb[8];
#pragma unroll
    for (int j = 0; j < 8; j++) bb[j] = __ldg(&bias[tx * 8 + j]);

#pragma unroll
    for (int rp = 0; rp < 4; rp++) {
        float ox[8], oy[8];
#pragma unroll
        for (int c = 0; c < 8; c++) {
            float2 f = unpack2(acc2[rp][c]);
            ox[c] = gelu_exact(f.x + bb[c]);
            oy[c] = gelu_exact(f.y + bb[c]);
        }
        int row0 = M0 + ty * 8 + rp * 2;
        *(float4*)&C[(size_t)row0 * 128 + tx * 8]           = make_float4(ox[0], ox[1], ox[2], ox[3]);
        *(float4*)&C[(size_t)row0 * 128 + tx * 8 + 4]       = make_float4(ox[4], ox[5], ox[6], ox[7]);
        *(float4*)&C[(size_t)(row0 + 1) * 128 + tx * 8]     = make_float4(oy[0], oy[1], oy[2], oy[3]);
        *(float4*)&C[(size_t)(row0 + 1) * 128 + tx * 8 + 4] = make_float4(oy[4], oy[5], oy[6], oy[7]);
    }
}

// ---------------- 5. fc GEMM (128 -> 64) + bias + GELU (f32x2) ---------------
__global__ __launch_bounds__(256, 2)
void fc_gemm_kernel(const float* __restrict__ A,
                    const float* __restrict__ B,
                    const float* __restrict__ bias,
                    float* __restrict__ C) {
    __shared__ float As[32 * 132];   // transposed A tile [k][m], pad 132
    __shared__ float Bs[32 * 64];

    int tid = threadIdx.x;
    int tx = tid & 15;     // 4 cols per thread
    int ty = tid >> 4;     // 8 rows per thread
    int M0 = blockIdx.x * 128;

    unsigned long long acc2[4][4];   // [row-pair][col]
#pragma unroll
    for (int r = 0; r < 4; r++)
#pragma unroll
        for (int c = 0; c < 4; c++) acc2[r][c] = 0ull;

    for (int kt = 0; kt < 4; kt++) {
        int kb = kt * 32;

        float4 av[4];
#pragma unroll
        for (int i = 0; i < 4; i++) {
            int f = tid + i * 256;
            int m = f >> 3, kq = f & 7;
            av[i] = __ldg((const float4*)&A[(size_t)(M0 + m) * 128 + kb + kq * 4]);
        }
        float4 bv[2];
#pragma unroll
        for (int i = 0; i < 2; i++) {
            int f = tid + i * 256;
            int k = f >> 4, c4 = f & 15;
            bv[i] = __ldg((const float4*)&B[(size_t)(kb + k) * 64 + c4 * 4]);
        }

        __syncthreads();
#pragma unroll
        for (int i = 0; i < 4; i++) {
            int f = tid + i * 256;
            int m = f >> 3, kq = f & 7;
            As[(kq * 4 + 0) * 132 + m] = av[i].x;
            As[(kq * 4 + 1) * 132 + m] = av[i].y;
            As[(kq * 4 + 2) * 132 + m] = av[i].z;
            As[(kq * 4 + 3) * 132 + m] = av[i].w;
        }
#pragma unroll
        for (int i = 0; i < 2; i++) {
            int f = tid + i * 256;
            int k = f >> 4, c4 = f & 15;
            *(float4*)&Bs[k * 64 + c4 * 4] = bv[i];
        }
        __syncthreads();

#pragma unroll 4
        for (int kk = 0; kk < 32; kk++) {
            ulonglong2 a01 = *(const ulonglong2*)&As[kk * 132 + ty * 8];
            ulonglong2 a23 = *(const ulonglong2*)&As[kk * 132 + ty * 8 + 4];
            float4 bf = *(const float4*)&Bs[kk * 64 + tx * 4];
            unsigned long long b2[4];
            b2[0] = pack2(bf.x, bf.x);
            b2[1] = pack2(bf.y, bf.y);
            b2[2] = pack2(bf.z, bf.z);
            b2[3] = pack2(bf.w, bf.w);
#pragma unroll
            for (int c = 0; c < 4; c++) {
                ffma2(acc2[0][c], a01.x, b2[c]);
                ffma2(acc2[1][c], a01.y, b2[c]);
                ffma2(acc2[2][c], a23.x, b2[c]);
                ffma2(acc2[3][c], a23.y, b2[c]);
            }
        }
    }

    float bb[4];
#pragma unroll
    for (int j = 0; j < 4; j++) bb[j] = __ldg(&bias[tx * 4 + j]);

#pragma unroll
    for (int r2 = 0; r2 < 4; r2++) {
        float ox[4], oy[4];
#pragma unroll
        for (int c = 0; c < 4; c++) {
            float2 f = unpack2(acc2[r2][c]);
            ox[c] = gelu_exact(f.x + bb[c]);
            oy[c] = gelu_exact(f.y + bb[c]);
        }
        int row0 = M0 + ty * 8 + r2 * 2;
        *(float4*)&C[(size_t)row0 * 64 + tx * 4]       = make_float4(ox[0], ox[1], ox[2], ox[3]);
        *(float4*)&C[(size_t)(row0 + 1) * 64 + tx * 4] = make_float4(oy[0], oy[1], oy[2], oy[3]);
    }
}

// ---------------- 6. GRU input gates ----------------------------------------
__global__ void gi_kernel(const float* __restrict__ W_ih,
                          const float* __restrict__ b_ih) {
    int idx  = blockIdx.x * blockDim.x + threadIdx.x;
    int node = idx >> 5;
    int lane = idx & 31;
    if (node >= NN) return;
    float2 v = *(const float2*)&g_hfc[(size_t)node * DIN + lane * 2];
    float d0 = v.x * W_ih[lane * 2] + v.y * W_ih[lane * 2 + 1];
    float d1 = v.x * W_ih[64 + lane * 2] + v.y * W_ih[64 + lane * 2 + 1];
    float d2 = v.x * W_ih[128 + lane * 2] + v.y * W_ih[128 + lane * 2 + 1];
#pragma unroll
    for (int o = 16; o > 0; o >>= 1) {
        d0 += __shfl_xor_sync(0xFFFFFFFFu, d0, o);
        d1 += __shfl_xor_sync(0xFFFFFFFFu, d1, o);
        d2 += __shfl_xor_sync(0xFFFFFFFFu, d2, o);
    }
    if (lane == 0) {
        g_gi[(size_t)node * 3 + 0] = d0 + b_ih[0];
        g_gi[(size_t)node * 3 + 1] = d1 + b_ih[1];
        g_gi[(size_t)node * 3 + 2] = d2 + b_ih[2];
    }
}

// ---------------- 7. GRU scan (H=1) + last-nonzero select -------------------
__global__ void gru_scan_kernel(const float* __restrict__ W_hh,
                                const float* __restrict__ b_hh,
                                const float* __restrict__ init,
                                float* __restrict__ out) {
    int g = blockIdx.x * blockDim.x + threadIdx.x;
    if (g >= NG) return;
    float whr = W_hh[0], whz = W_hh[1], whn = W_hh[2];
    float bhr = b_hh[0], bhz = b_hh[1], bhn = b_hh[2];
    float h = init[0];
    float v0 = 0.f, lastVal = 0.f, sum = 0.f;
    int lastIdx = -1;
    const float* gp = &g_gi[(size_t)g * 64 * 3];
    for (int t = 0; t < 64; t++) {
        float gir = gp[t * 3 + 0];
        float giz = gp[t * 3 + 1];
        float gin = gp[t * 3 + 2];
        float r = 1.0f / (1.0f + expf(-(gir + whr * h + bhr)));
        float z = 1.0f / (1.0f + expf(-(giz + whz * h + bhz)));
        float n = tanhf(gin + r * (whn * h + bhn));
        h = (1.0f - z) * n + z * h;
        float m = h;  // mask == 1 (every graph has exactly 64 nodes)
        if (t == 0) v0 = m;
        if (m != 0.0f) { lastIdx = t; lastVal = m; }
        sum += m;
    }
    out[g] = (sum > 0.0f && lastIdx >= 0) ? lastVal : v0;
}

// ---------------- launch -----------------------------------------------------
extern "C" void kernel_launch(void* const* d_in, const int* in_sizes, int n_in,
                              void* d_out, int out_size) {
    (void)in_sizes; (void)n_in; (void)out_size;

    const float* x       = (const float*)d_in[0];
    const float* emb     = (const float*)d_in[1];
    const float* W_rel1  = (const float*)d_in[2];
    const float* b_rel1  = (const float*)d_in[3];
    const float* W_root1 = (const float*)d_in[4];
    const float* W_rel2  = (const float*)d_in[5];
    const float* b_rel2  = (const float*)d_in[6];
    const float* W_root2 = (const float*)d_in[7];
    const float* W_rel3  = (const float*)d_in[8];
    const float* b_rel3  = (const float*)d_in[9];
    const float* W_root3 = (const float*)d_in[10];
    const float* W_fc    = (const float*)d_in[11];
    const float* b_fc    = (const float*)d_in[12];
    const float* W_ih    = (const float*)d_in[13];
    const float* W_hh    = (const float*)d_in[14];
    const float* b_ih    = (const float*)d_in[15];
    const float* b_hh    = (const float*)d_in[16];
    const float* init    = (const float*)d_in[17];
    const int*   ei      = (const int*)d_in[18];
    float*       out     = (float*)d_out;

    float *hA, *hB, *agg, *hfc;
    cudaGetSymbolAddress((void**)&hA,  g_hA);
    cudaGetSymbolAddress((void**)&hB,  g_hB);
    cudaGetSymbolAddress((void**)&agg, g_agg);
    cudaGetSymbolAddress((void**)&hfc, g_hfc);

    const int T = 256;

    // embedding + normalize, CSR build
    zero_deg_kernel<<<(NN + T - 1) / T, T>>>();
    embed_norm_kernel<<<NN / 8, T>>>(x, emb, hA);
    hist_kernel<<<NE / T, T>>>(ei);
    scan_phase1<<<SCAN_BLOCKS, SCAN_TPB>>>();
    scan_phase2<<<1, SCAN_BLOCKS>>>();
    scan_phase3<<<SCAN_BLOCKS, SCAN_TPB>>>();
    fill_kernel<<<NE / T, T>>>(ei);

    // conv1: hA -> hB
    aggregate_kernel<<<NN / 8, T>>>(hA);
    dual_gemm_gelu_kernel<<<NN / 128, T>>>(agg, hA, W_rel1, W_root1, b_rel1, hB);
    // conv2: hB -> hA
    aggregate_kernel<<<NN / 8, T>>>(hB);
    dual_gemm_gelu_kernel<<<NN / 128, T>>>(agg, hB, W_rel2, W_root2, b_rel2, hA);
    // conv3: hA -> hB
    aggregate_kernel<<<NN / 8, T>>>(hA);
    dual_gemm_gelu_kernel<<<NN / 128, T>>>(agg, hA, W_rel3, W_root3, b_rel3, hB);
    // fc: hB -> hfc
    fc_gemm_kernel<<<NN / 128, T>>>(hB, W_fc, b_fc, hfc);

    // GRU
    gi_kernel<<<NN / 8, T>>>(W_ih, b_ih);
    gru_scan_kernel<<<NG / T, T>>>(W_hh, b_hh, init, out);
}

// round 9
// speedup vs baseline: 1.5401x; 1.1954x over previous
#include <cuda_runtime.h>
#include <cuda_bf16.h>
#include <math.h>
#include <stdint.h>

// Problem constants (fixed by setup_inputs)
#define NN 131072      // nodes
#define NE 2097152     // edges
#define NG 2048        // graphs
#define DIN 64         // input_dim
#define DH  128        // hidden dim

#define SCAN_BLOCKS 512
#define SCAN_TPB    256          // SCAN_BLOCKS * SCAN_TPB == NN

// ---------------- scratch (device globals; no allocation allowed) ----------
__device__ float g_hA[(size_t)NN * DH];
__device__ float g_hB[(size_t)NN * DH];
__device__ float g_agg[(size_t)NN * DH];
__device__ float g_hfc[(size_t)NN * DIN];
__device__ float g_gi[(size_t)NN * 3];
__device__ int   g_deg[NN];
__device__ int   g_off[NN + 1];
__device__ int   g_cur[NN];
__device__ int   g_src[NE];
__device__ int   g_bsum[SCAN_BLOCKS];
__device__ int   g_boff[SCAN_BLOCKS];

__device__ __forceinline__ float gelu_exact(float x) {
    return 0.5f * x * (1.0f + erff(x * 0.70710678118654752f));
}

// split fp32 pair -> packed hi-bf16x2 and lo-bf16x2 (3-term emulation)
__device__ __forceinline__ void split2(float a, float b, uint32_t& hi, uint32_t& lo) {
    __nv_bfloat162 h2 = __floats2bfloat162_rn(a, b);
    float ra = a - __bfloat162float(h2.x);
    float rb = b - __bfloat162float(h2.y);
    __nv_bfloat162 l2 = __floats2bfloat162_rn(ra, rb);
    hi = *(uint32_t*)&h2;
    lo = *(uint32_t*)&l2;
}

// mma.sync m16n8k16 bf16 (sm_80 baseline PTX — compiles for plain sm_103)
__device__ __forceinline__ void mma_bf16(float* d, const uint32_t* a, const uint32_t* b) {
    asm volatile(
        "mma.sync.aligned.m16n8k16.row.col.f32.bf16.bf16.f32 "
        "{%0,%1,%2,%3}, {%4,%5,%6,%7}, {%8,%9}, {%0,%1,%2,%3};"
        : "+f"(d[0]), "+f"(d[1]), "+f"(d[2]), "+f"(d[3])
        : "r"(a[0]), "r"(a[1]), "r"(a[2]), "r"(a[3]), "r"(b[0]), "r"(b[1]));
}

// ---------------- 1. embed + concat + L2 normalize -> g_hA ------------------
__global__ void embed_norm_kernel(const float* __restrict__ x,
                                  const float* __restrict__ emb,
                                  float* __restrict__ hout) {
    int idx  = blockIdx.x * blockDim.x + threadIdx.x;
    int node = idx >> 5;
    int lane = idx & 31;
    if (node >= NN) return;

    const float* xr = x + (size_t)node * 65;
    int id = (int)xr[64];

    float v[4];
    int base = lane * 4;
#pragma unroll
    for (int j = 0; j < 4; j++) {
        int c = base + j;
        v[j] = (c < 64) ? xr[c] : emb[(size_t)id * 64 + (c - 64)];
    }
    float ss = v[0] * v[0] + v[1] * v[1] + v[2] * v[2] + v[3] * v[3];
#pragma unroll
    for (int o = 16; o > 0; o >>= 1) ss += __shfl_xor_sync(0xFFFFFFFFu, ss, o);
    float inv = 1.0f / sqrtf(ss);

    float4 o;
    o.x = v[0] * inv; o.y = v[1] * inv; o.z = v[2] * inv; o.w = v[3] * inv;
    *(float4*)&hout[(size_t)node * DH + base] = o;
}

// ---------------- 2. CSR build ----------------------------------------------
__global__ void zero_deg_kernel() {
    int i = blockIdx.x * blockDim.x + threadIdx.x;
    if (i < NN) g_deg[i] = 0;
}

__global__ void hist_kernel(const int* __restrict__ ei) {
    int e = blockIdx.x * blockDim.x + threadIdx.x;
    if (e < NE) atomicAdd(&g_deg[ei[NE + e]], 1);
}

__global__ void scan_phase1() {
    __shared__ int sh[SCAN_TPB];
    int b = blockIdx.x, t = threadIdx.x;
    sh[t] = g_deg[b * SCAN_TPB + t];
    __syncthreads();
#pragma unroll
    for (int d = SCAN_TPB / 2; d > 0; d >>= 1) {
        if (t < d) sh[t] += sh[t + d];
        __syncthreads();
    }
    if (t == 0) g_bsum[b] = sh[0];
}

__global__ void scan_phase2() {
    __shared__ int sh[SCAN_BLOCKS];
    int t = threadIdx.x;
    sh[t] = g_bsum[t];
    __syncthreads();
#pragma unroll
    for (int d = 1; d < SCAN_BLOCKS; d <<= 1) {
        int v = (t >= d) ? sh[t - d] : 0;
        __syncthreads();
        sh[t] += v;
        __syncthreads();
    }
    g_boff[t] = (t == 0) ? 0 : sh[t - 1];
}

__global__ void scan_phase3() {
    __shared__ int sh[SCAN_TPB];
    int b = blockIdx.x, t = threadIdx.x;
    int i = b * SCAN_TPB + t;
    int d = g_deg[i];
    sh[t] = d;
    __syncthreads();
#pragma unroll
    for (int s = 1; s < SCAN_TPB; s <<= 1) {
        int v = (t >= s) ? sh[t - s] : 0;
        __syncthreads();
        sh[t] += v;
        __syncthreads();
    }
    int off = g_boff[b] + sh[t] - d;   // exclusive
    g_off[i] = off;
    g_cur[i] = off;
    if (i == NN - 1) g_off[NN] = off + d;
}

__global__ void fill_kernel(const int* __restrict__ ei) {
    int e = blockIdx.x * blockDim.x + threadIdx.x;
    if (e < NE) {
        int s = ei[e];
        int d = ei[NE + e];
        int p = atomicAdd(&g_cur[d], 1);
        g_src[p] = s;
    }
}

// ---------------- 3. neighbor sum: agg[i] = sum_{j->i} h[j] ----------------
__global__ void aggregate_kernel(const float* __restrict__ hin) {
    int idx  = blockIdx.x * blockDim.x + threadIdx.x;
    int node = idx >> 5;
    int lane = idx & 31;
    if (node >= NN) return;
    int beg = g_off[node], end = g_off[node + 1];
    float4 acc = make_float4(0.f, 0.f, 0.f, 0.f);
    int e = beg;
#pragma unroll 1
    for (; e + 4 <= end; e += 4) {
        int s0 = g_src[e], s1 = g_src[e + 1], s2 = g_src[e + 2], s3 = g_src[e + 3];
        float4 v0 = __ldg((const float4*)&hin[(size_t)s0 * DH + lane * 4]);
        float4 v1 = __ldg((const float4*)&hin[(size_t)s1 * DH + lane * 4]);
        float4 v2 = __ldg((const float4*)&hin[(size_t)s2 * DH + lane * 4]);
        float4 v3 = __ldg((const float4*)&hin[(size_t)s3 * DH + lane * 4]);
        acc.x += v0.x; acc.y += v0.y; acc.z += v0.z; acc.w += v0.w;
        acc.x += v1.x; acc.y += v1.y; acc.z += v1.z; acc.w += v1.w;
        acc.x += v2.x; acc.y += v2.y; acc.z += v2.z; acc.w += v2.w;
        acc.x += v3.x; acc.y += v3.y; acc.z += v3.z; acc.w += v3.w;
    }
    for (; e < end; e++) {
        int s = g_src[e];
        float4 v = __ldg((const float4*)&hin[(size_t)s * DH + lane * 4]);
        acc.x += v.x; acc.y += v.y; acc.z += v.z; acc.w += v.w;
    }
    *(float4*)&g_agg[(size_t)node * DH + lane * 4] = acc;
}

// ======== 4. tensor-core GEMM via mma.sync (bf16 3-split) + bias + GELU =====
// C[i] = gelu( A1[i]@B1 (+ A2[i]@B2) + bias )
// A*: [NN,128] fp32 row-major; B*: [128,N] fp32 row-major.
// M-tile 64, 256 threads, 2 blocks/SM for stage/MMA overlap.
// smem layout (uint32 = bf16x2 pair along k): pad-68 rows, conflict-free frags.
#define PADW 68

template <int N, bool DUAL>
__global__ __launch_bounds__(256, 2)
void mma_gemm_kernel(const float* __restrict__ A1, const float* __restrict__ A2,
                     const float* __restrict__ B1, const float* __restrict__ B2,
                     const float* __restrict__ bias, float* __restrict__ C) {
    constexpr int NW = N / 4;        // cols per warp (32 or 16)
    constexpr int NF = NW / 8;       // n-frags per warp (4 or 2)
    extern __shared__ uint32_t smw[];
    uint32_t* Ahi = smw;                       // [64][PADW]
    uint32_t* Alo = Ahi + 64 * PADW;
    uint32_t* Bhi = Alo + 64 * PADW;           // [N][PADW]
    uint32_t* Blo = Bhi + N * PADW;

    int tid = threadIdx.x, wid = tid >> 5, lane = tid & 31;
    int wm = wid & 1, wn = wid >> 1;           // 2 x 4 warp grid
    int M0 = blockIdx.x * 64;
    int lq = lane >> 2, lr = lane & 3;

    float acc[2][NF][4];
#pragma unroll
    for (int mf = 0; mf < 2; mf++)
#pragma unroll
        for (int f = 0; f < NF; f++)
#pragma unroll
            for (int j = 0; j < 4; j++) acc[mf][f][j] = 0.f;

#pragma unroll
    for (int op = 0; op < (DUAL ? 2 : 1); op++) {
        const float* As = op ? A2 : A1;
        const float* Bs = op ? B2 : B1;

        __syncthreads();   // previous op's fragment reads done before overwrite

        // ---- stage A tile [64 rows x 128 k] -> hi/lo pairs ----
#pragma unroll
        for (int it = 0; it < 4; it++) {       // 1024 items
            int item = it * 256 + tid;
            int r = item >> 4, k8 = item & 15;
            const float* p = As + (size_t)(M0 + r) * 128 + k8 * 8;
            float4 v0 = __ldg((const float4*)p);
            float4 v1 = __ldg((const float4*)(p + 4));
            uint32_t h[4], l[4];
            split2(v0.x, v0.y, h[0], l[0]);
            split2(v0.z, v0.w, h[1], l[1]);
            split2(v1.x, v1.y, h[2], l[2]);
            split2(v1.z, v1.w, h[3], l[3]);
            int base = r * PADW + k8 * 4;
            *(uint4*)&Ahi[base] = make_uint4(h[0], h[1], h[2], h[3]);
            *(uint4*)&Alo[base] = make_uint4(l[0], l[1], l[2], l[3]);
        }
        // ---- stage B tile: W [128 x N] -> [n][k2] hi/lo pairs (transpose) ----
#pragma unroll
        for (int it = 0; it < N * 64 / 256; it++) {
            int item = it * 256 + tid;
            int n = item % N, k2 = item / N;
            float w0 = __ldg(&Bs[(size_t)(2 * k2) * N + n]);
            float w1 = __ldg(&Bs[(size_t)(2 * k2 + 1) * N + n]);
            uint32_t h, l;
            split2(w0, w1, h, l);
            Bhi[n * PADW + k2] = h;
            Blo[n * PADW + k2] = l;
        }
        __syncthreads();

        // ---- 3 passes: hi*hi, hi*lo, lo*hi ----
#pragma unroll
        for (int pass = 0; pass < 3; pass++) {
            const uint32_t* Ap = (pass == 2) ? Alo : Ahi;
            const uint32_t* Bp = (pass == 1) ? Blo : Bhi;
#pragma unroll
            for (int s = 0; s < 8; s++) {      // k-steps of 16
                uint32_t afr[2][4];
#pragma unroll
                for (int mf = 0; mf < 2; mf++) {
                    int r0 = wm * 32 + mf * 16 + lq;
                    afr[mf][0] = Ap[r0 * PADW + s * 8 + lr];
                    afr[mf][1] = Ap[(r0 + 8) * PADW + s * 8 + lr];
                    afr[mf][2] = Ap[r0 * PADW + s * 8 + 4 + lr];
                    afr[mf][3] = Ap[(r0 + 8) * PADW + s * 8 + 4 + lr];
                }
                uint32_t bfr[NF][2];
#pragma unroll
                for (int f = 0; f < NF; f++) {
                    int c0 = wn * NW + f * 8 + lq;
                    bfr[f][0] = Bp[c0 * PADW + s * 8 + lr];
                    bfr[f][1] = Bp[c0 * PADW + s * 8 + 4 + lr];
                }
#pragma unroll
                for (int mf = 0; mf < 2; mf++)
#pragma unroll
                    for (int f = 0; f < NF; f++)
                        mma_bf16(acc[mf][f], afr[mf], bfr[f]);
            }
        }
    }

    // ---- epilogue: bias + exact GELU, fragment-direct stores ----
#pragma unroll
    for (int mf = 0; mf < 2; mf++) {
        int r0 = M0 + wm * 32 + mf * 16 + lq;
#pragma unroll
        for (int f = 0; f < NF; f++) {
            int c = wn * NW + f * 8 + lr * 2;
            float b0 = __ldg(&bias[c]), b1 = __ldg(&bias[c + 1]);
            float2 o0, o1;
            o0.x = gelu_exact(acc[mf][f][0] + b0);
            o0.y = gelu_exact(acc[mf][f][1] + b1);
            o1.x = gelu_exact(acc[mf][f][2] + b0);
            o1.y = gelu_exact(acc[mf][f][3] + b1);
            *(float2*)&C[(size_t)r0 * N + c]       = o0;
            *(float2*)&C[(size_t)(r0 + 8) * N + c] = o1;
        }
    }
}

#define CONV_SMEM ((2 * 64 * PADW + 2 * 128 * PADW) * 4)   // 104448 B
#define FC_SMEM   ((2 * 64 * PADW + 2 * 64 * PADW) * 4)    //  69632 B

// ---------------- 5. GRU input gates ----------------------------------------
__global__ void gi_kernel(const float* __restrict__ W_ih,
                          const float* __restrict__ b_ih) {
    int idx  = blockIdx.x * blockDim.x + threadIdx.x;
    int node = idx >> 5;
    int lane = idx & 31;
    if (node >= NN) return;
    float2 v = *(const float2*)&g_hfc[(size_t)node * DIN + lane * 2];
    float d0 = v.x * W_ih[lane * 2] + v.y * W_ih[lane * 2 + 1];
    float d1 = v.x * W_ih[64 + lane * 2] + v.y * W_ih[64 + lane * 2 + 1];
    float d2 = v.x * W_ih[128 + lane * 2] + v.y * W_ih[128 + lane * 2 + 1];
#pragma unroll
    for (int o = 16; o > 0; o >>= 1) {
        d0 += __shfl_xor_sync(0xFFFFFFFFu, d0, o);
        d1 += __shfl_xor_sync(0xFFFFFFFFu, d1, o);
        d2 += __shfl_xor_sync(0xFFFFFFFFu, d2, o);
    }
    if (lane == 0) {
        g_gi[(size_t)node * 3 + 0] = d0 + b_ih[0];
        g_gi[(size_t)node * 3 + 1] = d1 + b_ih[1];
        g_gi[(size_t)node * 3 + 2] = d2 + b_ih[2];
    }
}

// ---------------- 6. GRU scan (H=1) + last-nonzero select -------------------
__global__ void gru_scan_kernel(const float* __restrict__ W_hh,
                                const float* __restrict__ b_hh,
                                const float* __restrict__ init,
                                float* __restrict__ out) {
    int g = blockIdx.x * blockDim.x + threadIdx.x;
    if (g >= NG) return;
    float whr = W_hh[0], whz = W_hh[1], whn = W_hh[2];
    float bhr = b_hh[0], bhz = b_hh[1], bhn = b_hh[2];
    float h = init[0];
    float v0 = 0.f, lastVal = 0.f, sum = 0.f;
    int lastIdx = -1;
    const float* gp = &g_gi[(size_t)g * 64 * 3];
    for (int t = 0; t < 64; t++) {
        float gir = gp[t * 3 + 0];
        float giz = gp[t * 3 + 1];
        float gin = gp[t * 3 + 2];
        float r = 1.0f / (1.0f + expf(-(gir + whr * h + bhr)));
        float z = 1.0f / (1.0f + expf(-(giz + whz * h + bhz)));
        float n = tanhf(gin + r * (whn * h + bhn));
        h = (1.0f - z) * n + z * h;
        float m = h;  // mask == 1 (every graph has exactly 64 nodes)
        if (t == 0) v0 = m;
        if (m != 0.0f) { lastIdx = t; lastVal = m; }
        sum += m;
    }
    out[g] = (sum > 0.0f && lastIdx >= 0) ? lastVal : v0;
}

// ---------------- launch -----------------------------------------------------
extern "C" void kernel_launch(void* const* d_in, const int* in_sizes, int n_in,
                              void* d_out, int out_size) {
    (void)in_sizes; (void)n_in; (void)out_size;

    const float* x       = (const float*)d_in[0];
    const float* emb     = (const float*)d_in[1];
    const float* W_rel1  = (const float*)d_in[2];
    const float* b_rel1  = (const float*)d_in[3];
    const float* W_root1 = (const float*)d_in[4];
    const float* W_rel2  = (const float*)d_in[5];
    const float* b_rel2  = (const float*)d_in[6];
    const float* W_root2 = (const float*)d_in[7];
    const float* W_rel3  = (const float*)d_in[8];
    const float* b_rel3  = (const float*)d_in[9];
    const float* W_root3 = (const float*)d_in[10];
    const float* W_fc    = (const float*)d_in[11];
    const float* b_fc    = (const float*)d_in[12];
    const float* W_ih    = (const float*)d_in[13];
    const float* W_hh    = (const float*)d_in[14];
    const float* b_ih    = (const float*)d_in[15];
    const float* b_hh    = (const float*)d_in[16];
    const float* init    = (const float*)d_in[17];
    const int*   ei      = (const int*)d_in[18];
    float*       out     = (float*)d_out;

    float *hA, *hB, *agg, *hfc;
    cudaGetSymbolAddress((void**)&hA,  g_hA);
    cudaGetSymbolAddress((void**)&hB,  g_hB);
    cudaGetSymbolAddress((void**)&agg, g_agg);
    cudaGetSymbolAddress((void**)&hfc, g_hfc);

    cudaFuncSetAttribute(mma_gemm_kernel<128, true>,
                         cudaFuncAttributeMaxDynamicSharedMemorySize, CONV_SMEM);
    cudaFuncSetAttribute(mma_gemm_kernel<64, false>,
                         cudaFuncAttributeMaxDynamicSharedMemorySize, FC_SMEM);

    const int T = 256;

    // embedding + normalize, CSR build
    zero_deg_kernel<<<(NN + T - 1) / T, T>>>();
    embed_norm_kernel<<<NN / 8, T>>>(x, emb, hA);
    hist_kernel<<<NE / T, T>>>(ei);
    scan_phase1<<<SCAN_BLOCKS, SCAN_TPB>>>();
    scan_phase2<<<1, SCAN_BLOCKS>>>();
    scan_phase3<<<SCAN_BLOCKS, SCAN_TPB>>>();
    fill_kernel<<<NE / T, T>>>(ei);

    // conv1: hA -> hB
    aggregate_kernel<<<NN / 8, T>>>(hA);
    mma_gemm_kernel<128, true><<<NN / 64, T, CONV_SMEM>>>(agg, hA, W_rel1, W_root1, b_rel1, hB);
    // conv2: hB -> hA
    aggregate_kernel<<<NN / 8, T>>>(hB);
    mma_gemm_kernel<128, true><<<NN / 64, T, CONV_SMEM>>>(agg, hB, W_rel2, W_root2, b_rel2, hA);
    // conv3: hA -> hB
    aggregate_kernel<<<NN / 8, T>>>(hA);
    mma_gemm_kernel<128, true><<<NN / 64, T, CONV_SMEM>>>(agg, hA, W_rel3, W_root3, b_rel3, hB);
    // fc: hB -> hfc
    mma_gemm_kernel<64, false><<<NN / 64, T, FC_SMEM>>>(hB, nullptr, W_fc, nullptr, b_fc, hfc);

    // GRU
    gi_kernel<<<NN / 8, T>>>(W_ih, b_ih);
    gru_scan_kernel<<<NG / T, T>>>(W_hh, b_hh, init, out);
}

// round 10
// speedup vs baseline: 1.5832x; 1.0280x over previous
#include <cuda_runtime.h>
#include <cuda_bf16.h>
#include <math.h>
#include <stdint.h>

// Problem constants (fixed by setup_inputs)
#define NN 131072      // nodes
#define NE 2097152     // edges
#define NG 2048        // graphs
#define DIN 64         // input_dim
#define DH  128        // hidden dim

#define SCAN_BLOCKS 512
#define SCAN_TPB    256          // SCAN_BLOCKS * SCAN_TPB == NN

// ---------------- scratch (device globals; no allocation allowed) ----------
__device__ float g_hA[(size_t)NN * DH];
__device__ float g_hB[(size_t)NN * DH];
__device__ float g_agg[(size_t)NN * DH];
__device__ float g_hfc[(size_t)NN * DIN];
__device__ float g_gi[(size_t)NN * 3];
__device__ int   g_deg[NN];
__device__ int   g_off[NN + 1];
__device__ int   g_cur[NN];
__device__ int   g_src[NE];
__device__ int   g_bsum[SCAN_BLOCKS];
__device__ int   g_boff[SCAN_BLOCKS];
// precomputed bf16 hi/lo weight tiles, layout [n][k2] (k2 packs k=2*k2,2*k2+1)
// slots: 0=rel1 1=root1 2=rel2 3=root2 4=rel3 5=root3 6=fc
__device__ uint32_t g_whi[7][128 * 64];
__device__ uint32_t g_wlo[7][128 * 64];

__device__ __forceinline__ float gelu_exact(float x) {
    return 0.5f * x * (1.0f + erff(x * 0.70710678118654752f));
}

// split fp32 pair -> packed hi-bf16x2 and lo-bf16x2 (3-term emulation)
__device__ __forceinline__ void split2(float a, float b, uint32_t& hi, uint32_t& lo) {
    __nv_bfloat162 h2 = __floats2bfloat162_rn(a, b);
    float ra = a - __bfloat162float(h2.x);
    float rb = b - __bfloat162float(h2.y);
    __nv_bfloat162 l2 = __floats2bfloat162_rn(ra, rb);
    hi = *(uint32_t*)&h2;
    lo = *(uint32_t*)&l2;
}

// mma.sync m16n8k16 bf16 (sm_80 baseline PTX — compiles for plain sm_103)
__device__ __forceinline__ void mma_bf16(float* d, const uint32_t* a, const uint32_t* b) {
    asm volatile(
        "mma.sync.aligned.m16n8k16.row.col.f32.bf16.bf16.f32 "
        "{%0,%1,%2,%3}, {%4,%5,%6,%7}, {%8,%9}, {%0,%1,%2,%3};"
        : "+f"(d[0]), "+f"(d[1]), "+f"(d[2]), "+f"(d[3])
        : "r"(a[0]), "r"(a[1]), "r"(a[2]), "r"(a[3]), "r"(b[0]), "r"(b[1]));
}

// ---------------- 0. one-time weight conversion ------------------------------
// W [128 x N] fp32 row-major -> hi/lo [N][64] uint32 (bf16x2 along k)
__global__ void convert_w_kernel(const float* __restrict__ W, int N, int slot) {
    int idx = blockIdx.x * blockDim.x + threadIdx.x;
    if (idx >= N * 64) return;
    int n = idx >> 6, k2 = idx & 63;
    float w0 = __ldg(&W[(size_t)(2 * k2) * N + n]);
    float w1 = __ldg(&W[(size_t)(2 * k2 + 1) * N + n]);
    uint32_t h, l;
    split2(w0, w1, h, l);
    g_whi[slot][n * 64 + k2] = h;
    g_wlo[slot][n * 64 + k2] = l;
}

// ---------------- 1. embed + concat + L2 normalize -> g_hA ------------------
__global__ void embed_norm_kernel(const float* __restrict__ x,
                                  const float* __restrict__ emb,
                                  float* __restrict__ hout) {
    int idx  = blockIdx.x * blockDim.x + threadIdx.x;
    int node = idx >> 5;
    int lane = idx & 31;
    if (node >= NN) return;

    const float* xr = x + (size_t)node * 65;
    int id = (int)xr[64];

    float v[4];
    int base = lane * 4;
#pragma unroll
    for (int j = 0; j < 4; j++) {
        int c = base + j;
        v[j] = (c < 64) ? xr[c] : emb[(size_t)id * 64 + (c - 64)];
    }
    float ss = v[0] * v[0] + v[1] * v[1] + v[2] * v[2] + v[3] * v[3];
#pragma unroll
    for (int o = 16; o > 0; o >>= 1) ss += __shfl_xor_sync(0xFFFFFFFFu, ss, o);
    float inv = 1.0f / sqrtf(ss);

    float4 o;
    o.x = v[0] * inv; o.y = v[1] * inv; o.z = v[2] * inv; o.w = v[3] * inv;
    *(float4*)&hout[(size_t)node * DH + base] = o;
}

// ---------------- 2. CSR build ----------------------------------------------
__global__ void zero_deg_kernel() {
    int i = blockIdx.x * blockDim.x + threadIdx.x;
    if (i < NN) g_deg[i] = 0;
}

__global__ void hist_kernel(const int* __restrict__ ei) {
    int e = blockIdx.x * blockDim.x + threadIdx.x;
    if (e < NE) atomicAdd(&g_deg[ei[NE + e]], 1);
}

__global__ void scan_phase1() {
    __shared__ int sh[SCAN_TPB];
    int b = blockIdx.x, t = threadIdx.x;
    sh[t] = g_deg[b * SCAN_TPB + t];
    __syncthreads();
#pragma unroll
    for (int d = SCAN_TPB / 2; d > 0; d >>= 1) {
        if (t < d) sh[t] += sh[t + d];
        __syncthreads();
    }
    if (t == 0) g_bsum[b] = sh[0];
}

__global__ void scan_phase2() {
    __shared__ int sh[SCAN_BLOCKS];
    int t = threadIdx.x;
    sh[t] = g_bsum[t];
    __syncthreads();
#pragma unroll
    for (int d = 1; d < SCAN_BLOCKS; d <<= 1) {
        int v = (t >= d) ? sh[t - d] : 0;
        __syncthreads();
        sh[t] += v;
        __syncthreads();
    }
    g_boff[t] = (t == 0) ? 0 : sh[t - 1];
}

__global__ void scan_phase3() {
    __shared__ int sh[SCAN_TPB];
    int b = blockIdx.x, t = threadIdx.x;
    int i = b * SCAN_TPB + t;
    int d = g_deg[i];
    sh[t] = d;
    __syncthreads();
#pragma unroll
    for (int s = 1; s < SCAN_TPB; s <<= 1) {
        int v = (t >= s) ? sh[t - s] : 0;
        __syncthreads();
        sh[t] += v;
        __syncthreads();
    }
    int off = g_boff[b] + sh[t] - d;   // exclusive
    g_off[i] = off;
    g_cur[i] = off;
    if (i == NN - 1) g_off[NN] = off + d;
}

__global__ void fill_kernel(const int* __restrict__ ei) {
    int e = blockIdx.x * blockDim.x + threadIdx.x;
    if (e < NE) {
        int s = ei[e];
        int d = ei[NE + e];
        int p = atomicAdd(&g_cur[d], 1);
        g_src[p] = s;
    }
}

// ---------------- 3. neighbor sum: agg[i] = sum_{j->i} h[j] ----------------
__global__ void aggregate_kernel(const float* __restrict__ hin) {
    int idx  = blockIdx.x * blockDim.x + threadIdx.x;
    int node = idx >> 5;
    int lane = idx & 31;
    if (node >= NN) return;
    int beg = g_off[node], end = g_off[node + 1];
    float4 acc = make_float4(0.f, 0.f, 0.f, 0.f);
    int e = beg;
#pragma unroll 1
    for (; e + 4 <= end; e += 4) {
        int s0 = g_src[e], s1 = g_src[e + 1], s2 = g_src[e + 2], s3 = g_src[e + 3];
        float4 v0 = __ldg((const float4*)&hin[(size_t)s0 * DH + lane * 4]);
        float4 v1 = __ldg((const float4*)&hin[(size_t)s1 * DH + lane * 4]);
        float4 v2 = __ldg((const float4*)&hin[(size_t)s2 * DH + lane * 4]);
        float4 v3 = __ldg((const float4*)&hin[(size_t)s3 * DH + lane * 4]);
        acc.x += v0.x; acc.y += v0.y; acc.z += v0.z; acc.w += v0.w;
        acc.x += v1.x; acc.y += v1.y; acc.z += v1.z; acc.w += v1.w;
        acc.x += v2.x; acc.y += v2.y; acc.z += v2.z; acc.w += v2.w;
        acc.x += v3.x; acc.y += v3.y; acc.z += v3.z; acc.w += v3.w;
    }
    for (; e < end; e++) {
        int s = g_src[e];
        float4 v = __ldg((const float4*)&hin[(size_t)s * DH + lane * 4]);
        acc.x += v.x; acc.y += v.y; acc.z += v.z; acc.w += v.w;
    }
    *(float4*)&g_agg[(size_t)node * DH + lane * 4] = acc;
}

// ======== 4. tensor-core GEMM via mma.sync (bf16 3-split) + bias + GELU =====
// C[i] = gelu( A1[i]@W1 (+ A2[i]@W2) + bias ); weights preconverted to bf16
// hi/lo [N][64] tiles. M-tile 64, 256 threads, 2 blocks/SM.
#define PADW 68

template <int N, bool DUAL>
__global__ __launch_bounds__(256, 2)
void mma_gemm_kernel(const float* __restrict__ A1, const float* __restrict__ A2,
                     const uint32_t* __restrict__ bh1, const uint32_t* __restrict__ bl1,
                     const uint32_t* __restrict__ bh2, const uint32_t* __restrict__ bl2,
                     const float* __restrict__ bias, float* __restrict__ C) {
    constexpr int NW = N / 4;        // cols per warp (32 or 16)
    constexpr int NF = NW / 8;       // n-frags per warp (4 or 2)
    extern __shared__ uint32_t smw[];
    uint32_t* Ahi = smw;                       // [64][PADW]
    uint32_t* Alo = Ahi + 64 * PADW;
    uint32_t* Bhi = Alo + 64 * PADW;           // [N][PADW]
    uint32_t* Blo = Bhi + N * PADW;

    int tid = threadIdx.x, wid = tid >> 5, lane = tid & 31;
    int wm = wid & 1, wn = wid >> 1;           // 2 x 4 warp grid
    int M0 = blockIdx.x * 64;
    int lq = lane >> 2, lr = lane & 3;

    float acc[2][NF][4];
#pragma unroll
    for (int mf = 0; mf < 2; mf++)
#pragma unroll
        for (int f = 0; f < NF; f++)
#pragma unroll
            for (int j = 0; j < 4; j++) acc[mf][f][j] = 0.f;

#pragma unroll
    for (int op = 0; op < (DUAL ? 2 : 1); op++) {
        const float* As = op ? A2 : A1;
        const uint32_t* bh = op ? bh2 : bh1;
        const uint32_t* bl = op ? bl2 : bl1;

        __syncthreads();   // previous op's fragment reads done before overwrite

        // ---- stage A tile [64 rows x 128 k] -> hi/lo pairs ----
#pragma unroll
        for (int it = 0; it < 4; it++) {       // 1024 items
            int item = it * 256 + tid;
            int r = item >> 4, k8 = item & 15;
            const float* p = As + (size_t)(M0 + r) * 128 + k8 * 8;
            float4 v0 = __ldg((const float4*)p);
            float4 v1 = __ldg((const float4*)(p + 4));
            uint32_t h[4], l[4];
            split2(v0.x, v0.y, h[0], l[0]);
            split2(v0.z, v0.w, h[1], l[1]);
            split2(v1.x, v1.y, h[2], l[2]);
            split2(v1.z, v1.w, h[3], l[3]);
            int base = r * PADW + k8 * 4;
            *(uint4*)&Ahi[base] = make_uint4(h[0], h[1], h[2], h[3]);
            *(uint4*)&Alo[base] = make_uint4(l[0], l[1], l[2], l[3]);
        }
        // ---- stage B tile: plain uint4 copy of preconverted [n][64] ----
#pragma unroll
        for (int it = 0; it < N / 16; it++) {  // N*16 items
            int item = it * 256 + tid;
            int n = item >> 4, q = item & 15;
            *(uint4*)&Bhi[n * PADW + q * 4] = *(const uint4*)&bh[n * 64 + q * 4];
            *(uint4*)&Blo[n * PADW + q * 4] = *(const uint4*)&bl[n * 64 + q * 4];
        }
        __syncthreads();

        // ---- 3 passes: hi*hi, hi*lo, lo*hi ----
#pragma unroll
        for (int pass = 0; pass < 3; pass++) {
            const uint32_t* Ap = (pass == 2) ? Alo : Ahi;
            const uint32_t* Bp = (pass == 1) ? Blo : Bhi;
#pragma unroll
            for (int s = 0; s < 8; s++) {      // k-steps of 16
                uint32_t afr[2][4];
#pragma unroll
                for (int mf = 0; mf < 2; mf++) {
                    int r0 = wm * 32 + mf * 16 + lq;
                    afr[mf][0] = Ap[r0 * PADW + s * 8 + lr];
                    afr[mf][1] = Ap[(r0 + 8) * PADW + s * 8 + lr];
                    afr[mf][2] = Ap[r0 * PADW + s * 8 + 4 + lr];
                    afr[mf][3] = Ap[(r0 + 8) * PADW + s * 8 + 4 + lr];
                }
                uint32_t bfr[NF][2];
#pragma unroll
                for (int f = 0; f < NF; f++) {
                    int c0 = wn * NW + f * 8 + lq;
                    bfr[f][0] = Bp[c0 * PADW + s * 8 + lr];
                    bfr[f][1] = Bp[c0 * PADW + s * 8 + 4 + lr];
                }
#pragma unroll
                for (int mf = 0; mf < 2; mf++)
#pragma unroll
                    for (int f = 0; f < NF; f++)
                        mma_bf16(acc[mf][f], afr[mf], bfr[f]);
            }
        }
    }

    // ---- epilogue: bias + exact GELU, fragment-direct stores ----
#pragma unroll
    for (int mf = 0; mf < 2; mf++) {
        int r0 = M0 + wm * 32 + mf * 16 + lq;
#pragma unroll
        for (int f = 0; f < NF; f++) {
            int c = wn * NW + f * 8 + lr * 2;
            float b0 = __ldg(&bias[c]), b1 = __ldg(&bias[c + 1]);
            float2 o0, o1;
            o0.x = gelu_exact(acc[mf][f][0] + b0);
            o0.y = gelu_exact(acc[mf][f][1] + b1);
            o1.x = gelu_exact(acc[mf][f][2] + b0);
            o1.y = gelu_exact(acc[mf][f][3] + b1);
            *(float2*)&C[(size_t)r0 * N + c]       = o0;
            *(float2*)&C[(size_t)(r0 + 8) * N + c] = o1;
        }
    }
}

#define CONV_SMEM ((2 * 64 * PADW + 2 * 128 * PADW) * 4)   // 104448 B
#define FC_SMEM   ((2 * 64 * PADW + 2 * 64 * PADW) * 4)    //  69632 B

// ---------------- 5. GRU input gates ----------------------------------------
__global__ void gi_kernel(const float* __restrict__ W_ih,
                          const float* __restrict__ b_ih) {
    int idx  = blockIdx.x * blockDim.x + threadIdx.x;
    int node = idx >> 5;
    int lane = idx & 31;
    if (node >= NN) return;
    float2 v = *(const float2*)&g_hfc[(size_t)node * DIN + lane * 2];
    float d0 = v.x * W_ih[lane * 2] + v.y * W_ih[lane * 2 + 1];
    float d1 = v.x * W_ih[64 + lane * 2] + v.y * W_ih[64 + lane * 2 + 1];
    float d2 = v.x * W_ih[128 + lane * 2] + v.y * W_ih[128 + lane * 2 + 1];
#pragma unroll
    for (int o = 16; o > 0; o >>= 1) {
        d0 += __shfl_xor_sync(0xFFFFFFFFu, d0, o);
        d1 += __shfl_xor_sync(0xFFFFFFFFu, d1, o);
        d2 += __shfl_xor_sync(0xFFFFFFFFu, d2, o);
    }
    if (lane == 0) {
        g_gi[(size_t)node * 3 + 0] = d0 + b_ih[0];
        g_gi[(size_t)node * 3 + 1] = d1 + b_ih[1];
        g_gi[(size_t)node * 3 + 2] = d2 + b_ih[2];
    }
}

// ---------------- 6. GRU scan (H=1) + last-nonzero select -------------------
__global__ void gru_scan_kernel(const float* __restrict__ W_hh,
                                const float* __restrict__ b_hh,
                                const float* __restrict__ init,
                                float* __restrict__ out) {
    int g = blockIdx.x * blockDim.x + threadIdx.x;
    if (g >= NG) return;
    float whr = W_hh[0], whz = W_hh[1], whn = W_hh[2];
    float bhr = b_hh[0], bhz = b_hh[1], bhn = b_hh[2];
    float h = init[0];
    float v0 = 0.f, lastVal = 0.f, sum = 0.f;
    int lastIdx = -1;
    const float* gp = &g_gi[(size_t)g * 64 * 3];
    for (int t = 0; t < 64; t++) {
        float gir = gp[t * 3 + 0];
        float giz = gp[t * 3 + 1];
        float gin = gp[t * 3 + 2];
        float r = 1.0f / (1.0f + expf(-(gir + whr * h + bhr)));
        float z = 1.0f / (1.0f + expf(-(giz + whz * h + bhz)));
        float n = tanhf(gin + r * (whn * h + bhn));
        h = (1.0f - z) * n + z * h;
        float m = h;  // mask == 1 (every graph has exactly 64 nodes)
        if (t == 0) v0 = m;
        if (m != 0.0f) { lastIdx = t; lastVal = m; }
        sum += m;
    }
    out[g] = (sum > 0.0f && lastIdx >= 0) ? lastVal : v0;
}

// ---------------- launch -----------------------------------------------------
extern "C" void kernel_launch(void* const* d_in, const int* in_sizes, int n_in,
                              void* d_out, int out_size) {
    (void)in_sizes; (void)n_in; (void)out_size;

    const float* x       = (const float*)d_in[0];
    const float* emb     = (const float*)d_in[1];
    const float* W_rel1  = (const float*)d_in[2];
    const float* b_rel1  = (const float*)d_in[3];
    const float* W_root1 = (const float*)d_in[4];
    const float* W_rel2  = (const float*)d_in[5];
    const float* b_rel2  = (const float*)d_in[6];
    const float* W_root2 = (const float*)d_in[7];
    const float* W_rel3  = (const float*)d_in[8];
    const float* b_rel3  = (const float*)d_in[9];
    const float* W_root3 = (const float*)d_in[10];
    const float* W_fc    = (const float*)d_in[11];
    const float* b_fc    = (const float*)d_in[12];
    const float* W_ih    = (const float*)d_in[13];
    const float* W_hh    = (const float*)d_in[14];
    const float* b_ih    = (const float*)d_in[15];
    const float* b_hh    = (const float*)d_in[16];
    const float* init    = (const float*)d_in[17];
    const int*   ei      = (const int*)d_in[18];
    float*       out     = (float*)d_out;

    float *hA, *hB, *agg, *hfc;
    uint32_t (*whi)[128 * 64]; uint32_t (*wlo)[128 * 64];
    cudaGetSymbolAddress((void**)&hA,  g_hA);
    cudaGetSymbolAddress((void**)&hB,  g_hB);
    cudaGetSymbolAddress((void**)&agg, g_agg);
    cudaGetSymbolAddress((void**)&hfc, g_hfc);
    cudaGetSymbolAddress((void**)&whi, g_whi);
    cudaGetSymbolAddress((void**)&wlo, g_wlo);

    cudaFuncSetAttribute(mma_gemm_kernel<128, true>,
                         cudaFuncAttributeMaxDynamicSharedMemorySize, CONV_SMEM);
    cudaFuncSetAttribute(mma_gemm_kernel<64, false>,
                         cudaFuncAttributeMaxDynamicSharedMemorySize, FC_SMEM);

    const int T = 256;

    // one-time weight conversions (independent of everything else)
    convert_w_kernel<<<32, T>>>(W_rel1,  128, 0);
    convert_w_kernel<<<32, T>>>(W_root1, 128, 1);
    convert_w_kernel<<<32, T>>>(W_rel2,  128, 2);
    convert_w_kernel<<<32, T>>>(W_root2, 128, 3);
    convert_w_kernel<<<32, T>>>(W_rel3,  128, 4);
    convert_w_kernel<<<32, T>>>(W_root3, 128, 5);
    convert_w_kernel<<<16, T>>>(W_fc,     64, 6);

    // embedding + normalize, CSR build
    zero_deg_kernel<<<(NN + T - 1) / T, T>>>();
    embed_norm_kernel<<<NN / 8, T>>>(x, emb, hA);
    hist_kernel<<<NE / T, T>>>(ei);
    scan_phase1<<<SCAN_BLOCKS, SCAN_TPB>>>();
    scan_phase2<<<1, SCAN_BLOCKS>>>();
    scan_phase3<<<SCAN_BLOCKS, SCAN_TPB>>>();
    fill_kernel<<<NE / T, T>>>(ei);

    // conv1: hA -> hB
    aggregate_kernel<<<NN / 8, T>>>(hA);
    mma_gemm_kernel<128, true><<<NN / 64, T, CONV_SMEM>>>(
        agg, hA, whi[0], wlo[0], whi[1], wlo[1], b_rel1, hB);
    // conv2: hB -> hA
    aggregate_kernel<<<NN / 8, T>>>(hB);
    mma_gemm_kernel<128, true><<<NN / 64, T, CONV_SMEM>>>(
        agg, hB, whi[2], wlo[2], whi[3], wlo[3], b_rel2, hA);
    // conv3: hA -> hB
    aggregate_kernel<<<NN / 8, T>>>(hA);
    mma_gemm_kernel<128, true><<<NN / 64, T, CONV_SMEM>>>(
        agg, hA, whi[4], wlo[4], whi[5], wlo[5], b_rel3, hB);
    // fc: hB -> hfc
    mma_gemm_kernel<64, false><<<NN / 64, T, FC_SMEM>>>(
        hB, nullptr, whi[6], wlo[6], nullptr, nullptr, b_fc, hfc);

    // GRU
    gi_kernel<<<NN / 8, T>>>(W_ih, b_ih);
    gru_scan_kernel<<<NG / T, T>>>(W_hh, b_hh, init, out);
}

// round 11
// speedup vs baseline: 1.9699x; 1.2443x over previous
#include <cuda_runtime.h>
#include <cuda_bf16.h>
#include <math.h>
#include <stdint.h>

// Problem constants (fixed by setup_inputs)
#define NN 131072      // nodes
#define NE 2097152     // edges
#define NG 2048        // graphs
#define DIN 64         // input_dim
#define DH  128        // hidden dim

#define SCAN_BLOCKS 512
#define SCAN_TPB    256          // SCAN_BLOCKS * SCAN_TPB == NN

// ---------------- scratch (device globals; no allocation allowed) ----------
__device__ float g_hA[(size_t)NN * DH];
__device__ float g_hB[(size_t)NN * DH];
__device__ float g_agg[(size_t)NN * DH];
__device__ float g_hfc[(size_t)NN * DIN];
__device__ float g_gi[(size_t)NN * 3];
__device__ int   g_deg[NN];
__device__ int   g_off[NN + 1];
__device__ int   g_cur[NN];
__device__ int   g_src[NE];
__device__ int   g_bsum[SCAN_BLOCKS];
__device__ int   g_boff[SCAN_BLOCKS];
// precomputed bf16 hi/lo weight tiles, layout [n][k2] (k2 packs k=2*k2,2*k2+1)
// slots: 0=rel1 1=root1 2=rel2 3=root2 4=rel3 5=root3 6=fc
__device__ uint32_t g_whi[7][128 * 64];
__device__ uint32_t g_wlo[7][128 * 64];

__device__ __forceinline__ float gelu_exact(float x) {
    return 0.5f * x * (1.0f + erff(x * 0.70710678118654752f));
}

// split fp32 pair -> packed hi-bf16x2 and lo-bf16x2 (3-term emulation)
__device__ __forceinline__ void split2(float a, float b, uint32_t& hi, uint32_t& lo) {
    __nv_bfloat162 h2 = __floats2bfloat162_rn(a, b);
    float ra = a - __bfloat162float(h2.x);
    float rb = b - __bfloat162float(h2.y);
    __nv_bfloat162 l2 = __floats2bfloat162_rn(ra, rb);
    hi = *(uint32_t*)&h2;
    lo = *(uint32_t*)&l2;
}

// mma.sync m16n8k16 bf16 (sm_80 baseline PTX — compiles for plain sm_103)
__device__ __forceinline__ void mma_bf16(float* d, const uint32_t* a, const uint32_t* b) {
    asm volatile(
        "mma.sync.aligned.m16n8k16.row.col.f32.bf16.bf16.f32 "
        "{%0,%1,%2,%3}, {%4,%5,%6,%7}, {%8,%9}, {%0,%1,%2,%3};"
        : "+f"(d[0]), "+f"(d[1]), "+f"(d[2]), "+f"(d[3])
        : "r"(a[0]), "r"(a[1]), "r"(a[2]), "r"(a[3]), "r"(b[0]), "r"(b[1]));
}

#define LDM_X4(r0, r1, r2, r3, addr) \
    asm volatile("ldmatrix.sync.aligned.m8n8.x4.shared.b16 {%0,%1,%2,%3}, [%4];" \
        : "=r"(r0), "=r"(r1), "=r"(r2), "=r"(r3) : "r"(addr))

__device__ __forceinline__ uint32_t smem_u32(const void* p) {
    uint32_t a;
    asm("{ .reg .u64 t; cvta.to.shared.u64 t, %1; cvt.u32.u64 %0, t; }"
        : "=r"(a) : "l"(p));
    return a;
}

// ---------------- 0. one-time weight conversion (all 7 in one launch) -------
// W [128 x N] fp32 row-major -> hi/lo [N][64] uint32 (bf16x2 along k)
__global__ void convert_all_kernel(const float* __restrict__ W0, const float* __restrict__ W1,
                                   const float* __restrict__ W2, const float* __restrict__ W3,
                                   const float* __restrict__ W4, const float* __restrict__ W5,
                                   const float* __restrict__ W6) {
    int idx = blockIdx.x * blockDim.x + threadIdx.x;   // 53248 items
    const float* Wp;
    int slot, within, N;
    if (idx < 6 * 8192) {
        slot = idx >> 13; within = idx & 8191; N = 128;
        const float* tab[6] = {W0, W1, W2, W3, W4, W5};
        Wp = tab[slot];
    } else {
        if (idx >= 6 * 8192 + 4096) return;
        slot = 6; within = idx - 6 * 8192; N = 64;
        Wp = W6;
    }
    int n = within >> 6, k2 = within & 63;
    float w0 = __ldg(&Wp[(size_t)(2 * k2) * N + n]);
    float w1 = __ldg(&Wp[(size_t)(2 * k2 + 1) * N + n]);
    uint32_t h, l;
    split2(w0, w1, h, l);
    g_whi[slot][n * 64 + k2] = h;
    g_wlo[slot][n * 64 + k2] = l;
}

// ---------------- 1. embed + concat + L2 normalize -> g_hA ------------------
__global__ void embed_norm_kernel(const float* __restrict__ x,
                                  const float* __restrict__ emb,
                                  float* __restrict__ hout) {
    int idx  = blockIdx.x * blockDim.x + threadIdx.x;
    int node = idx >> 5;
    int lane = idx & 31;
    if (node >= NN) return;

    const float* xr = x + (size_t)node * 65;
    int id = (int)xr[64];

    float v[4];
    int base = lane * 4;
#pragma unroll
    for (int j = 0; j < 4; j++) {
        int c = base + j;
        v[j] = (c < 64) ? xr[c] : emb[(size_t)id * 64 + (c - 64)];
    }
    float ss = v[0] * v[0] + v[1] * v[1] + v[2] * v[2] + v[3] * v[3];
#pragma unroll
    for (int o = 16; o > 0; o >>= 1) ss += __shfl_xor_sync(0xFFFFFFFFu, ss, o);
    float inv = 1.0f / sqrtf(ss);

    float4 o;
    o.x = v[0] * inv; o.y = v[1] * inv; o.z = v[2] * inv; o.w = v[3] * inv;
    *(float4*)&hout[(size_t)node * DH + base] = o;
}

// ---------------- 2. CSR build ----------------------------------------------
__global__ void zero_deg_kernel() {
    int i = blockIdx.x * blockDim.x + threadIdx.x;
    if (i < NN) g_deg[i] = 0;
}

__global__ void hist_kernel(const int* __restrict__ ei) {
    int e = blockIdx.x * blockDim.x + threadIdx.x;
    if (e < NE) atomicAdd(&g_deg[ei[NE + e]], 1);
}

__global__ void scan_phase1() {
    __shared__ int sh[SCAN_TPB];
    int b = blockIdx.x, t = threadIdx.x;
    sh[t] = g_deg[b * SCAN_TPB + t];
    __syncthreads();
#pragma unroll
    for (int d = SCAN_TPB / 2; d > 0; d >>= 1) {
        if (t < d) sh[t] += sh[t + d];
        __syncthreads();
    }
    if (t == 0) g_bsum[b] = sh[0];
}

__global__ void scan_phase2() {
    __shared__ int sh[SCAN_BLOCKS];
    int t = threadIdx.x;
    sh[t] = g_bsum[t];
    __syncthreads();
#pragma unroll
    for (int d = 1; d < SCAN_BLOCKS; d <<= 1) {
        int v = (t >= d) ? sh[t - d] : 0;
        __syncthreads();
        sh[t] += v;
        __syncthreads();
    }
    g_boff[t] = (t == 0) ? 0 : sh[t - 1];
}

__global__ void scan_phase3() {
    __shared__ int sh[SCAN_TPB];
    int b = blockIdx.x, t = threadIdx.x;
    int i = b * SCAN_TPB + t;
    int d = g_deg[i];
    sh[t] = d;
    __syncthreads();
#pragma unroll
    for (int s = 1; s < SCAN_TPB; s <<= 1) {
        int v = (t >= s) ? sh[t - s] : 0;
        __syncthreads();
        sh[t] += v;
        __syncthreads();
    }
    int off = g_boff[b] + sh[t] - d;   // exclusive
    g_off[i] = off;
    g_cur[i] = off;
    if (i == NN - 1) g_off[NN] = off + d;
}

__global__ void fill_kernel(const int* __restrict__ ei) {
    int e = blockIdx.x * blockDim.x + threadIdx.x;
    if (e < NE) {
        int s = ei[e];
        int d = ei[NE + e];
        int p = atomicAdd(&g_cur[d], 1);
        g_src[p] = s;
    }
}

// ---------------- 3. neighbor sum: agg[i] = sum_{j->i} h[j] ----------------
__global__ void aggregate_kernel(const float* __restrict__ hin) {
    int idx  = blockIdx.x * blockDim.x + threadIdx.x;
    int node = idx >> 5;
    int lane = idx & 31;
    if (node >= NN) return;
    int beg = g_off[node], end = g_off[node + 1];
    float4 acc = make_float4(0.f, 0.f, 0.f, 0.f);
    int e = beg;
#pragma unroll 1
    for (; e + 4 <= end; e += 4) {
        int s0 = g_src[e], s1 = g_src[e + 1], s2 = g_src[e + 2], s3 = g_src[e + 3];
        float4 v0 = __ldg((const float4*)&hin[(size_t)s0 * DH + lane * 4]);
        float4 v1 = __ldg((const float4*)&hin[(size_t)s1 * DH + lane * 4]);
        float4 v2 = __ldg((const float4*)&hin[(size_t)s2 * DH + lane * 4]);
        float4 v3 = __ldg((const float4*)&hin[(size_t)s3 * DH + lane * 4]);
        acc.x += v0.x; acc.y += v0.y; acc.z += v0.z; acc.w += v0.w;
        acc.x += v1.x; acc.y += v1.y; acc.z += v1.z; acc.w += v1.w;
        acc.x += v2.x; acc.y += v2.y; acc.z += v2.z; acc.w += v2.w;
        acc.x += v3.x; acc.y += v3.y; acc.z += v3.z; acc.w += v3.w;
    }
    for (; e < end; e++) {
        int s = g_src[e];
        float4 v = __ldg((const float4*)&hin[(size_t)s * DH + lane * 4]);
        acc.x += v.x; acc.y += v.y; acc.z += v.z; acc.w += v.w;
    }
    *(float4*)&g_agg[(size_t)node * DH + lane * 4] = acc;
}

// ======== 4. tensor-core GEMM via mma.sync + ldmatrix (bf16 3-split) ========
// C[i] = gelu( A1[i]@W1 (+ A2[i]@W2) + bias ); weights preconverted bf16 hi/lo.
// M-tile 64, 256 threads, 2 blocks/SM. Fragments loaded via ldmatrix.x4.
#define PADW 68

template <int N, bool DUAL>
__global__ __launch_bounds__(256, 2)
void mma_gemm_kernel(const float* __restrict__ A1, const float* __restrict__ A2,
                     const uint32_t* __restrict__ bh1, const uint32_t* __restrict__ bl1,
                     const uint32_t* __restrict__ bh2, const uint32_t* __restrict__ bl2,
                     const float* __restrict__ bias, float* __restrict__ C) {
    constexpr int NW = N / 4;        // cols per warp (32 or 16)
    constexpr int NF = NW / 8;       // n-frags per warp (4 or 2)
    extern __shared__ uint32_t smw[];
    uint32_t* Ahi = smw;                       // [64][PADW]
    uint32_t* Alo = Ahi + 64 * PADW;
    uint32_t* Bhi = Alo + 64 * PADW;           // [N][PADW]
    uint32_t* Blo = Bhi + N * PADW;

    int tid = threadIdx.x, wid = tid >> 5, lane = tid & 31;
    int wm = wid & 1, wn = wid >> 1;           // 2 x 4 warp grid
    int M0 = blockIdx.x * 64;
    int lq = lane >> 2, lr = lane & 3;

    // ldmatrix per-lane smem byte offsets (within each tile array)
    uint32_t AhiU = smem_u32(Ahi), AloU = smem_u32(Alo);
    uint32_t BhiU = smem_u32(Bhi), BloU = smem_u32(Blo);
    // A x4: lanes 0-15 -> m rows (l&15), k2 base; lanes 16-31 -> same rows, k2+4
    uint32_t aoff0 = (uint32_t)((wm * 32 + (lane & 15)) * PADW + (lane >> 4) * 4) * 4;
    uint32_t aoff1 = aoff0 + 16 * PADW * 4;
    // B x4: M0=f.b0 (n l&7), M1=f.b1 (k2+4), M2=f'.b0 (n+8), M3=f'.b1
    uint32_t boff[NF / 2];
#pragma unroll
    for (int fp = 0; fp < NF / 2; fp++)
        boff[fp] = (uint32_t)((wn * NW + fp * 16 + (lane & 7) + ((lane >> 4) & 1) * 8) * PADW
                              + ((lane >> 3) & 1) * 4) * 4;

    float acc[2][NF][4];
#pragma unroll
    for (int mf = 0; mf < 2; mf++)
#pragma unroll
        for (int f = 0; f < NF; f++)
#pragma unroll
            for (int j = 0; j < 4; j++) acc[mf][f][j] = 0.f;

#pragma unroll
    for (int op = 0; op < (DUAL ? 2 : 1); op++) {
        const float* As = op ? A2 : A1;
        const uint32_t* bh = op ? bh2 : bh1;
        const uint32_t* bl = op ? bl2 : bl1;

        __syncthreads();   // previous op's fragment reads done before overwrite

        // ---- stage A tile [64 rows x 128 k] -> hi/lo pairs ----
#pragma unroll
        for (int it = 0; it < 4; it++) {       // 1024 items
            int item = it * 256 + tid;
            int r = item >> 4, k8 = item & 15;
            const float* p = As + (size_t)(M0 + r) * 128 + k8 * 8;
            float4 v0 = __ldg((const float4*)p);
            float4 v1 = __ldg((const float4*)(p + 4));
            uint32_t h[4], l[4];
            split2(v0.x, v0.y, h[0], l[0]);
            split2(v0.z, v0.w, h[1], l[1]);
            split2(v1.x, v1.y, h[2], l[2]);
            split2(v1.z, v1.w, h[3], l[3]);
            int base = r * PADW + k8 * 4;
            *(uint4*)&Ahi[base] = make_uint4(h[0], h[1], h[2], h[3]);
            *(uint4*)&Alo[base] = make_uint4(l[0], l[1], l[2], l[3]);
        }
        // ---- stage B tile: plain uint4 copy of preconverted [n][64] ----
#pragma unroll
        for (int it = 0; it < N / 16; it++) {  // N*16 items
            int item = it * 256 + tid;
            int n = item >> 4, q = item & 15;
            *(uint4*)&Bhi[n * PADW + q * 4] = *(const uint4*)&bh[n * 64 + q * 4];
            *(uint4*)&Blo[n * PADW + q * 4] = *(const uint4*)&bl[n * 64 + q * 4];
        }
        __syncthreads();

        // ---- 8 k-steps; per step load hi+lo frags once, 3 mma groups ----
#pragma unroll
        for (int s = 0; s < 8; s++) {
            uint32_t sb = s * 32;              // s*8 k2-words = 32 bytes
            uint32_t ah[2][4], al[2][4], bhf[NF][2], blf[NF][2];
            LDM_X4(ah[0][0], ah[0][1], ah[0][2], ah[0][3], AhiU + aoff0 + sb);
            LDM_X4(ah[1][0], ah[1][1], ah[1][2], ah[1][3], AhiU + aoff1 + sb);
            LDM_X4(al[0][0], al[0][1], al[0][2], al[0][3], AloU + aoff0 + sb);
            LDM_X4(al[1][0], al[1][1], al[1][2], al[1][3], AloU + aoff1 + sb);
#pragma unroll
            for (int fp = 0; fp < NF / 2; fp++) {
                LDM_X4(bhf[2 * fp][0], bhf[2 * fp][1], bhf[2 * fp + 1][0], bhf[2 * fp + 1][1],
                       BhiU + boff[fp] + sb);
                LDM_X4(blf[2 * fp][0], blf[2 * fp][1], blf[2 * fp + 1][0], blf[2 * fp + 1][1],
                       BloU + boff[fp] + sb);
            }
#pragma unroll
            for (int mf = 0; mf < 2; mf++)
#pragma unroll
                for (int f = 0; f < NF; f++)
                    mma_bf16(acc[mf][f], ah[mf], bhf[f]);
#pragma unroll
            for (int mf = 0; mf < 2; mf++)
#pragma unroll
                for (int f = 0; f < NF; f++)
                    mma_bf16(acc[mf][f], ah[mf], blf[f]);
#pragma unroll
            for (int mf = 0; mf < 2; mf++)
#pragma unroll
                for (int f = 0; f < NF; f++)
                    mma_bf16(acc[mf][f], al[mf], bhf[f]);
        }
    }

    // ---- epilogue: bias + exact GELU, fragment-direct stores ----
#pragma unroll
    for (int mf = 0; mf < 2; mf++) {
        int r0 = M0 + wm * 32 + mf * 16 + lq;
#pragma unroll
        for (int f = 0; f < NF; f++) {
            int c = wn * NW + f * 8 + lr * 2;
            float b0 = __ldg(&bias[c]), b1 = __ldg(&bias[c + 1]);
            float2 o0, o1;
            o0.x = gelu_exact(acc[mf][f][0] + b0);
            o0.y = gelu_exact(acc[mf][f][1] + b1);
            o1.x = gelu_exact(acc[mf][f][2] + b0);
            o1.y = gelu_exact(acc[mf][f][3] + b1);
            *(float2*)&C[(size_t)r0 * N + c]       = o0;
            *(float2*)&C[(size_t)(r0 + 8) * N + c] = o1;
        }
    }
}

#define CONV_SMEM ((2 * 64 * PADW + 2 * 128 * PADW) * 4)   // 104448 B
#define FC_SMEM   ((2 * 64 * PADW + 2 * 64 * PADW) * 4)    //  69632 B

// ---------------- 5. GRU input gates ----------------------------------------
__global__ void gi_kernel(const float* __restrict__ W_ih,
                          const float* __restrict__ b_ih) {
    int idx  = blockIdx.x * blockDim.x + threadIdx.x;
    int node = idx >> 5;
    int lane = idx & 31;
    if (node >= NN) return;
    float2 v = *(const float2*)&g_hfc[(size_t)node * DIN + lane * 2];
    float d0 = v.x * W_ih[lane * 2] + v.y * W_ih[lane * 2 + 1];
    float d1 = v.x * W_ih[64 + lane * 2] + v.y * W_ih[64 + lane * 2 + 1];
    float d2 = v.x * W_ih[128 + lane * 2] + v.y * W_ih[128 + lane * 2 + 1];
#pragma unroll
    for (int o = 16; o > 0; o >>= 1) {
        d0 += __shfl_xor_sync(0xFFFFFFFFu, d0, o);
        d1 += __shfl_xor_sync(0xFFFFFFFFu, d1, o);
        d2 += __shfl_xor_sync(0xFFFFFFFFu, d2, o);
    }
    if (lane == 0) {
        g_gi[(size_t)node * 3 + 0] = d0 + b_ih[0];
        g_gi[(size_t)node * 3 + 1] = d1 + b_ih[1];
        g_gi[(size_t)node * 3 + 2] = d2 + b_ih[2];
    }
}

// ---------------- 6. GRU scan (H=1) + last-nonzero select -------------------
__global__ void gru_scan_kernel(const float* __restrict__ W_hh,
                                const float* __restrict__ b_hh,
                                const float* __restrict__ init,
                                float* __restrict__ out) {
    int g = blockIdx.x * blockDim.x + threadIdx.x;
    if (g >= NG) return;
    float whr = W_hh[0], whz = W_hh[1], whn = W_hh[2];
    float bhr = b_hh[0], bhz = b_hh[1], bhn = b_hh[2];
    float h = init[0];
    float v0 = 0.f, lastVal = 0.f, sum = 0.f;
    int lastIdx = -1;
    const float* gp = &g_gi[(size_t)g * 64 * 3];
    for (int t = 0; t < 64; t++) {
        float gir = gp[t * 3 + 0];
        float giz = gp[t * 3 + 1];
        float gin = gp[t * 3 + 2];
        float r = 1.0f / (1.0f + expf(-(gir + whr * h + bhr)));
        float z = 1.0f / (1.0f + expf(-(giz + whz * h + bhz)));
        float n = tanhf(gin + r * (whn * h + bhn));
        h = (1.0f - z) * n + z * h;
        float m = h;  // mask == 1 (every graph has exactly 64 nodes)
        if (t == 0) v0 = m;
        if (m != 0.0f) { lastIdx = t; lastVal = m; }
        sum += m;
    }
    out[g] = (sum > 0.0f && lastIdx >= 0) ? lastVal : v0;
}

// ---------------- launch -----------------------------------------------------
extern "C" void kernel_launch(void* const* d_in, const int* in_sizes, int n_in,
                              void* d_out, int out_size) {
    (void)in_sizes; (void)n_in; (void)out_size;

    const float* x       = (const float*)d_in[0];
    const float* emb     = (const float*)d_in[1];
    const float* W_rel1  = (const float*)d_in[2];
    const float* b_rel1  = (const float*)d_in[3];
    const float* W_root1 = (const float*)d_in[4];
    const float* W_rel2  = (const float*)d_in[5];
    const float* b_rel2  = (const float*)d_in[6];
    const float* W_root2 = (const float*)d_in[7];
    const float* W_rel3  = (const float*)d_in[8];
    const float* b_rel3  = (const float*)d_in[9];
    const float* W_root3 = (const float*)d_in[10];
    const float* W_fc    = (const float*)d_in[11];
    const float* b_fc    = (const float*)d_in[12];
    const float* W_ih    = (const float*)d_in[13];
    const float* W_hh    = (const float*)d_in[14];
    const float* b_ih    = (const float*)d_in[15];
    const float* b_hh    = (const float*)d_in[16];
    const float* init    = (const float*)d_in[17];
    const int*   ei      = (const int*)d_in[18];
    float*       out     = (float*)d_out;

    float *hA, *hB, *agg, *hfc;
    uint32_t (*whi)[128 * 64]; uint32_t (*wlo)[128 * 64];
    cudaGetSymbolAddress((void**)&hA,  g_hA);
    cudaGetSymbolAddress((void**)&hB,  g_hB);
    cudaGetSymbolAddress((void**)&agg, g_agg);
    cudaGetSymbolAddress((void**)&hfc, g_hfc);
    cudaGetSymbolAddress((void**)&whi, g_whi);
    cudaGetSymbolAddress((void**)&wlo, g_wlo);

    cudaFuncSetAttribute(mma_gemm_kernel<128, true>,
                         cudaFuncAttributeMaxDynamicSharedMemorySize, CONV_SMEM);
    cudaFuncSetAttribute(mma_gemm_kernel<64, false>,
                         cudaFuncAttributeMaxDynamicSharedMemorySize, FC_SMEM);

    const int T = 256;

    // CSR build first (profiler -s 5 -c 1 lands on fill_kernel)
    zero_deg_kernel<<<(NN + T - 1) / T, T>>>();
    hist_kernel<<<NE / T, T>>>(ei);
    scan_phase1<<<SCAN_BLOCKS, SCAN_TPB>>>();
    scan_phase2<<<1, SCAN_BLOCKS>>>();
    scan_phase3<<<SCAN_BLOCKS, SCAN_TPB>>>();
    fill_kernel<<<NE / T, T>>>(ei);

    // embedding + one-shot weight conversion
    embed_norm_kernel<<<NN / 8, T>>>(x, emb, hA);
    convert_all_kernel<<<208, T>>>(W_rel1, W_root1, W_rel2, W_root2, W_rel3, W_root3, W_fc);

    // conv1: hA -> hB
    aggregate_kernel<<<NN / 8, T>>>(hA);
    mma_gemm_kernel<128, true><<<NN / 64, T, CONV_SMEM>>>(
        agg, hA, whi[0], wlo[0], whi[1], wlo[1], b_rel1, hB);
    // conv2: hB -> hA
    aggregate_kernel<<<NN / 8, T>>>(hB);
    mma_gemm_kernel<128, true><<<NN / 64, T, CONV_SMEM>>>(
        agg, hB, whi[2], wlo[2], whi[3], wlo[3], b_rel2, hA);
    // conv3: hA -> hB
    aggregate_kernel<<<NN / 8, T>>>(hA);
    mma_gemm_kernel<128, true><<<NN / 64, T, CONV_SMEM>>>(
        agg, hA, whi[4], wlo[4], whi[5], wlo[5], b_rel3, hB);
    // fc: hB -> hfc
    mma_gemm_kernel<64, false><<<NN / 64, T, FC_SMEM>>>(
        hB, nullptr, whi[6], wlo[6], nullptr, nullptr, b_fc, hfc);

    // GRU
    gi_kernel<<<NN / 8, T>>>(W_ih, b_ih);
    gru_scan_kernel<<<NG / T, T>>>(W_hh, b_hh, init, out);
}